// round 11
// baseline (speedup 1.0000x reference)
#include <cuda_runtime.h>
#include <math.h>
#include <float.h>
#include <stdint.h>

// Problem constants
#define NQ 512
#define DIM 768
#define ND 100000
#define TOPK 8
#define SDOC 128

#define TILE_N 128
#define NT 782                    // ceil(100000/128)
#define NDPAD (NT * 128)          // 100096
#define NC (NT * 8)               // candidates per query
#define NCAND 16

#define KSTAGES 6                 // K=768 in 128-wide int8 stages
#define STG_A 16384               // 128 rows x 128B
#define STG_BYTES 32768           // A + B per stage
#define NSLOT 3
#define TILE_BYTES_PER (KSTAGES * STG_A)   // 96KB per 128-row tile

// Output layout (fp32 concat, reference return order)
#define OFF_TOK   0u
#define OFF_MASK  524288u
#define OFF_SCORE 1048576u
#define OFF_IDS   1052672u
#define OFF_EMB   1056768u

typedef unsigned long long ull;

// Scratch (device globals)
__device__ float g_qn[NQ * DIM];
__device__ __align__(128) unsigned char g_qnT[4 * TILE_BYTES_PER];
__device__ __align__(128) unsigned char g_dkT[(size_t)NT * TILE_BYTES_PER];  // 76.9MB int8
__device__ float g_dinv[ND];
__device__ float g_dqs[NDPAD];    // per-doc dequant factor (1/S_d), 0 for pad
__device__ ull   g_ck[(size_t)NQ * NC];
__device__ int   g_cand[NQ * NCAND];
__device__ float g_topv[NQ * TOPK];
__device__ int   g_topi[NQ * TOPK];

// ---------------------------------------------------------------------------
// helpers
// ---------------------------------------------------------------------------
__device__ __forceinline__ uint32_t smem_u32(const void* p) {
    uint32_t a;
    asm("{ .reg .u64 t; cvta.to.shared.u64 t, %1; cvt.u32.u64 %0, t; }"
        : "=r"(a) : "l"(p));
    return a;
}
__device__ __forceinline__ uint64_t gmem_u64(const void* p) {
    uint64_t r;
    asm("cvta.to.global.u64 %0, %1;" : "=l"(r) : "l"(p));
    return r;
}
__device__ __forceinline__ uint32_t f2sort(float f) {
    uint32_t u = __float_as_uint(f);
    return (u & 0x80000000u) ? ~u : (u | 0x80000000u);
}
// int8 tiled+swizzled byte offset: element c (0..767) of row (0..127)
__device__ __forceinline__ size_t tiled_off8(int row, int c) {
    int stage = c >> 7;
    int cc = c & 127;
    int chunk = (cc >> 4) ^ (row & 7);
    return (size_t)stage * STG_A + (size_t)row * 128 + chunk * 16 + (cc & 15);
}

#define MBAR_INIT(a, c) \
    asm volatile("mbarrier.init.shared.b64 [%0], %1;" :: "r"(a), "r"(c) : "memory")
#define MBAR_EXPECT(a, n) \
    asm volatile("mbarrier.arrive.expect_tx.shared.b64 _, [%0], %1;" :: "r"(a), "r"(n) : "memory")
__device__ __forceinline__ void mbar_wait(uint32_t mbar, uint32_t parity) {
    asm volatile(
        "{\n\t.reg .pred P1;\n\t"
        "WAIT_LOOP_%=:\n\t"
        "mbarrier.try_wait.parity.acquire.cta.shared::cta.b64 P1, [%0], %1, 0x989680;\n\t"
        "@P1 bra.uni WAIT_DONE_%=;\n\t"
        "bra.uni WAIT_LOOP_%=;\n\t"
        "WAIT_DONE_%=:\n\t}"
        :: "r"(mbar), "r"(parity) : "memory");
}
__device__ __forceinline__ void bulk_cp(uint32_t dst, uint64_t src, uint32_t mbar) {
    asm volatile(
        "cp.async.bulk.shared::cluster.global.mbarrier::complete_tx::bytes "
        "[%0], [%1], %2, [%3];"
        :: "r"(dst), "l"(src), "r"(16384), "r"(mbar) : "memory");
}

#define LDSM4(r0,r1,r2,r3,a) \
    asm volatile("ldmatrix.sync.aligned.m8n8.x4.shared.b16 {%0,%1,%2,%3}, [%4];" \
                 : "=r"(r0),"=r"(r1),"=r"(r2),"=r"(r3) : "r"(a))

__device__ __forceinline__ void mma16832(int* c, uint32_t a0, uint32_t a1,
                                         uint32_t a2, uint32_t a3,
                                         uint32_t b0, uint32_t b1) {
    asm volatile(
        "mma.sync.aligned.m16n8k32.row.col.s32.s8.s8.s32 "
        "{%0,%1,%2,%3}, {%4,%5,%6,%7}, {%8,%9}, {%0,%1,%2,%3};"
        : "+r"(c[0]), "+r"(c[1]), "+r"(c[2]), "+r"(c[3])
        : "r"(a0), "r"(a1), "r"(a2), "r"(a3), "r"(b0), "r"(b1));
}

__device__ __forceinline__ signed char q8(float v, float S) {
    float r = fminf(fmaxf(v * S, -127.f), 127.f);
    return (signed char)__float2int_rn(r);
}

// ---------------------------------------------------------------------------
// Query normalize -> fp32 (for rescore) + int8 tiled (for GEMM)
// ---------------------------------------------------------------------------
__global__ __launch_bounds__(256) void qnorm_kernel(const float* __restrict__ q) {
    int r = blockIdx.x;
    __shared__ float red[256];
    __shared__ float redm[256];
    __shared__ float s_inv, s_scale;
    float v0 = q[r * DIM + threadIdx.x];
    float v1 = q[r * DIM + threadIdx.x + 256];
    float v2 = q[r * DIM + threadIdx.x + 512];
    red[threadIdx.x]  = v0 * v0 + v1 * v1 + v2 * v2;
    redm[threadIdx.x] = fmaxf(fabsf(v0), fmaxf(fabsf(v1), fabsf(v2)));
    __syncthreads();
    for (int st = 128; st >= 1; st >>= 1) {
        if (threadIdx.x < st) {
            red[threadIdx.x] += red[threadIdx.x + st];
            redm[threadIdx.x] = fmaxf(redm[threadIdx.x], redm[threadIdx.x + st]);
        }
        __syncthreads();
    }
    if (threadIdx.x == 0) {
        float inv = 1.0f / fmaxf(sqrtf(red[0]), 1e-12f);
        s_inv = inv;
        s_scale = 127.0f / fmaxf(redm[0] * inv, 1e-6f);
    }
    __syncthreads();
    float inv = s_inv, S = s_scale;
    int tile = r >> 7, row = r & 127;
    unsigned char* obase = g_qnT + (size_t)tile * TILE_BYTES_PER;
    #pragma unroll
    for (int e = 0; e < 3; e++) {
        int c = threadIdx.x + e * 256;
        float v = (e == 0 ? v0 : (e == 1 ? v1 : v2)) * inv;
        g_qn[r * DIM + c] = v;
        *(signed char*)(obase + tiled_off8(row, c)) = q8(v, S);
    }
}

// ---------------------------------------------------------------------------
// Doc prep: norm + int8 quant into tiled layout; per-doc dequant factor
// ---------------------------------------------------------------------------
__global__ __launch_bounds__(256) void docprep_kernel(const float* __restrict__ dk) {
    int d = blockIdx.x;               // 0..NDPAD-1
    int tile = d >> 7, row = d & 127;
    unsigned char* obase = g_dkT + (size_t)tile * TILE_BYTES_PER;
    if (d >= ND) {
        #pragma unroll
        for (int e = 0; e < 3; e++) {
            int c = threadIdx.x + e * 256;
            *(signed char*)(obase + tiled_off8(row, c)) = 0;
        }
        if (threadIdx.x == 0) g_dqs[d] = 0.f;
        return;
    }
    const float* srow = dk + (size_t)d * DIM;
    float v0 = srow[threadIdx.x];
    float v1 = srow[threadIdx.x + 256];
    float v2 = srow[threadIdx.x + 512];
    __shared__ float red[256];
    __shared__ float redm[256];
    __shared__ float s_inv, s_scale;
    red[threadIdx.x]  = v0 * v0 + v1 * v1 + v2 * v2;
    redm[threadIdx.x] = fmaxf(fabsf(v0), fmaxf(fabsf(v1), fabsf(v2)));
    __syncthreads();
    for (int st = 128; st >= 1; st >>= 1) {
        if (threadIdx.x < st) {
            red[threadIdx.x] += red[threadIdx.x + st];
            redm[threadIdx.x] = fmaxf(redm[threadIdx.x], redm[threadIdx.x + st]);
        }
        __syncthreads();
    }
    if (threadIdx.x == 0) {
        float inv = 1.0f / fmaxf(sqrtf(red[0]), 1e-12f);
        s_inv = inv;
        g_dinv[d] = inv;
        float S = 127.0f / fmaxf(redm[0] * inv, 1e-6f);
        s_scale = S;
        g_dqs[d] = 1.0f / S;
    }
    __syncthreads();
    float inv = s_inv, S = s_scale;
    #pragma unroll
    for (int e = 0; e < 3; e++) {
        int c = threadIdx.x + e * 256;
        float v = (e == 0 ? v0 : (e == 1 ? v1 : v2)) * inv;
        *(signed char*)(obase + tiled_off8(row, c)) = q8(v, S);
    }
}

// ---------------------------------------------------------------------------
// Phase-1 GEMM: int8 s8s8s32 m16n8k32, 128q x 128docs per CTA, 4 warps
// (warp tile 64x64), K=768 as 6 stages of 128, bulk-copy 3-slot pipeline.
// Fused per-query top-8 candidate epilogue with per-doc dequant.
// ---------------------------------------------------------------------------
#define SCORE_LD 130

__global__ __launch_bounds__(128, 2) void score_gemm_mma() {
    extern __shared__ char dynsm[];
    __shared__ __align__(8) ull s_full[NSLOT];

    const int tid  = threadIdx.x;
    const int lane = tid & 31;
    const int wid  = tid >> 5;
    const int wm   = (wid & 1) * 64;
    const int wn   = (wid >> 1) * 64;
    const int qBase = blockIdx.x * 128;
    const int nBase = blockIdx.y * TILE_N;
    const int valid = min(TILE_N, ND - nBase);

    const uint32_t raw = smem_u32(dynsm);
    const uint32_t smbase = (raw + 127u) & ~127u;
    char* bufp = dynsm + (smbase - raw);

    const uint64_t srcA = gmem_u64(g_qnT) + (size_t)blockIdx.x * TILE_BYTES_PER;
    const uint64_t srcB = gmem_u64(g_dkT) + (size_t)blockIdx.y * TILE_BYTES_PER;

    if (tid == 0) {
        #pragma unroll
        for (int i = 0; i < NSLOT; i++) MBAR_INIT(smem_u32(&s_full[i]), 1);
    }
    __syncthreads();

    #define ISSUE(s) do { \
        int _slot = (s) % NSLOT; \
        uint32_t _mb = smem_u32(&s_full[_slot]); \
        uint32_t _dst = smbase + _slot * STG_BYTES; \
        MBAR_EXPECT(_mb, STG_BYTES); \
        bulk_cp(_dst, srcA + (size_t)(s) * STG_A, _mb); \
        bulk_cp(_dst + STG_A, srcB + (size_t)(s) * STG_A, _mb); \
    } while (0)

    if (tid == 0) { ISSUE(0); ISSUE(1); ISSUE(2); }

    int acc[4][8][4];
    #pragma unroll
    for (int mi = 0; mi < 4; mi++)
        #pragma unroll
        for (int ni = 0; ni < 8; ni++)
            #pragma unroll
            for (int e = 0; e < 4; e++) acc[mi][ni][e] = 0;

    for (int s = 0; s < KSTAGES; s++) {
        const int slot = s % NSLOT;
        mbar_wait(smem_u32(&s_full[slot]), (s / NSLOT) & 1);
        const uint32_t buf = smbase + slot * STG_BYTES;

        #pragma unroll
        for (int kk = 0; kk < 4; kk++) {          // four K32 blocks per stage
            uint32_t aF[4][4], bF[4][4];
            // A: matrices [r0-7,k0-15][r8-15,k0-15][r0-7,k16-31][r8-15,k16-31]
            #pragma unroll
            for (int mi = 0; mi < 4; mi++) {
                int row = wm + mi * 16 + (lane & 7) + ((lane >> 3) & 1) * 8;
                int chunk = (kk * 2 + (lane >> 4)) ^ (row & 7);
                LDSM4(aF[mi][0], aF[mi][1], aF[mi][2], aF[mi][3],
                      buf + row * 128 + chunk * 16);
            }
            // B: matrices [n0-7,k0-15][n0-7,k16-31][n8-15,k0-15][n8-15,k16-31]
            #pragma unroll
            for (int nb = 0; nb < 4; nb++) {
                int row = wn + nb * 16 + (lane & 7) + ((lane >> 4) & 1) * 8;
                int chunk = (kk * 2 + ((lane >> 3) & 1)) ^ (row & 7);
                LDSM4(bF[nb][0], bF[nb][1], bF[nb][2], bF[nb][3],
                      buf + STG_A + row * 128 + chunk * 16);
            }
            #pragma unroll
            for (int mi = 0; mi < 4; mi++)
                #pragma unroll
                for (int n8 = 0; n8 < 8; n8++)
                    mma16832(acc[mi][n8],
                             aF[mi][0], aF[mi][1], aF[mi][2], aF[mi][3],
                             bF[n8 >> 1][(n8 & 1) * 2], bF[n8 >> 1][(n8 & 1) * 2 + 1]);
        }
        __syncthreads();
        if (tid == 0 && s + NSLOT < KSTAGES) ISSUE(s + NSLOT);
    }
    #undef ISSUE

    // --- epilogue: int scores -> smem, dequant table, per-query top-8
    int* sci = (int*)bufp;                              // [128][SCORE_LD]
    float* dqv = (float*)(bufp + 128 * SCORE_LD * 4);   // [128]
    const int mrow = lane >> 2;
    const int ncol = (lane & 3) * 2;
    #pragma unroll
    for (int mi = 0; mi < 4; mi++) {
        #pragma unroll
        for (int n8 = 0; n8 < 8; n8++) {
            int m = wm + mi * 16 + mrow;
            int n = wn + n8 * 8 + ncol;
            *(int2*)&sci[m * SCORE_LD + n] = make_int2(acc[mi][n8][0], acc[mi][n8][1]);
            *(int2*)&sci[(m + 8) * SCORE_LD + n] = make_int2(acc[mi][n8][2], acc[mi][n8][3]);
        }
    }
    dqv[tid] = g_dqs[nBase + tid];
    __syncthreads();

    // one thread per query row: top-8 keys over 128 columns
    ull key[8];
    #pragma unroll
    for (int j = 0; j < 8; j++) key[j] = 0;
    for (int col = 0; col < TILE_N; col++) {
        if (col >= valid) break;
        float v = (float)sci[tid * SCORE_LD + col] * dqv[col];
        ull k = ((ull)f2sort(v) << 32) | (uint32_t)(~(uint32_t)(nBase + col));
        if (k > key[7]) {
            bool placed = false;
            #pragma unroll
            for (int p = 7; p >= 0; p--) {
                bool upper = (p > 0) && (k > key[p - 1]);
                if (!placed) {
                    if (upper) key[p] = key[p - 1];
                    else       { key[p] = k; placed = true; }
                }
            }
        }
    }
    {
        size_t base = ((size_t)(qBase + tid) * NT + blockIdx.y) * 8;
        #pragma unroll
        for (int j = 0; j < 8; j++) g_ck[base + j] = key[j];
    }
}

// ---------------------------------------------------------------------------
// Merge: per query, tree-merge candidate keys -> top-16
// ---------------------------------------------------------------------------
__device__ __forceinline__ void merge16(ull* dst, const ull* a, const ull* b,
                                        int la, int lb) {
    int ia = 0, ib = 0;
    #pragma unroll
    for (int o = 0; o < 16; o++) {
        bool ta = (ib >= lb) || (ia < la && a[ia] >= b[ib]);
        dst[o] = ta ? a[ia++] : b[ib++];
    }
}

__global__ __launch_bounds__(256) void merge_kernel() {
    const int q = blockIdx.x;
    const int tid = threadIdx.x;
    __shared__ ull bufA[2048];
    __shared__ ull bufB[2048];

    ull loc[8];
    #pragma unroll
    for (int j = 0; j < 8; j++) loc[j] = 0;
    const ull* ck = g_ck + (size_t)q * NC;
    for (int i = tid; i < NC; i += 256) {
        ull k = ck[i];
        if (k > loc[7]) {
            bool placed = false;
            #pragma unroll
            for (int p = 7; p >= 0; p--) {
                bool upper = (p > 0) && (k > loc[p - 1]);
                if (!placed) {
                    if (upper) loc[p] = loc[p - 1];
                    else       { loc[p] = k; placed = true; }
                }
            }
        }
    }
    #pragma unroll
    for (int j = 0; j < 8; j++) bufA[tid * 8 + j] = loc[j];
    __syncthreads();

    if (tid < 128) merge16(&bufB[tid * 16], &bufA[2 * tid * 8], &bufA[(2 * tid + 1) * 8], 8, 8);
    __syncthreads();
    if (tid < 64) merge16(&bufA[tid * 16], &bufB[2 * tid * 16], &bufB[(2 * tid + 1) * 16], 16, 16);
    __syncthreads();
    if (tid < 32) merge16(&bufB[tid * 16], &bufA[2 * tid * 16], &bufA[(2 * tid + 1) * 16], 16, 16);
    __syncthreads();
    if (tid < 16) merge16(&bufA[tid * 16], &bufB[2 * tid * 16], &bufB[(2 * tid + 1) * 16], 16, 16);
    __syncthreads();
    if (tid < 8)  merge16(&bufB[tid * 16], &bufA[2 * tid * 16], &bufA[(2 * tid + 1) * 16], 16, 16);
    __syncthreads();
    if (tid < 4)  merge16(&bufA[tid * 16], &bufB[2 * tid * 16], &bufB[(2 * tid + 1) * 16], 16, 16);
    __syncthreads();
    if (tid < 2)  merge16(&bufB[tid * 16], &bufA[2 * tid * 16], &bufA[(2 * tid + 1) * 16], 16, 16);
    __syncthreads();
    if (tid < 1)  merge16(&bufA[0], &bufB[0], &bufB[16], 16, 16);
    __syncthreads();

    if (tid < NCAND)
        g_cand[q * NCAND + tid] = (int)(~(uint32_t)(bufA[tid] & 0xFFFFFFFFull));
}

// ---------------------------------------------------------------------------
// Exact fp32 rescore of 16 candidates + final top-8 (tie -> lower index)
// ---------------------------------------------------------------------------
__global__ __launch_bounds__(256) void rescore_kernel(const float* __restrict__ dk) {
    const int q = blockIdx.x;
    const int tid = threadIdx.x;
    const int wid = tid >> 5, lane = tid & 31;
    __shared__ float qrow[DIM];
    __shared__ float sval[NCAND];
    __shared__ int   sidx[NCAND];

    for (int i = tid; i < DIM; i += 256) qrow[i] = g_qn[q * DIM + i];
    __syncthreads();

    #pragma unroll
    for (int rep = 0; rep < 2; rep++) {
        int c = wid + rep * 8;
        int doc = g_cand[q * NCAND + c];
        const float* drow = dk + (size_t)doc * DIM;
        float s = 0.f;
        #pragma unroll
        for (int e = 0; e < DIM / 32; e++)
            s = fmaf(qrow[lane + e * 32], drow[lane + e * 32], s);
        #pragma unroll
        for (int off = 16; off >= 1; off >>= 1)
            s += __shfl_xor_sync(0xFFFFFFFFu, s, off);
        if (lane == 0) { sval[c] = s * g_dinv[doc]; sidx[c] = doc; }
    }
    __syncthreads();

    if (tid == 0) {
        bool used[NCAND];
        #pragma unroll
        for (int i = 0; i < NCAND; i++) used[i] = false;
        for (int j = 0; j < TOPK; j++) {
            float bv = -FLT_MAX; int bi = 0x7FFFFFFF; int bp = -1;
            for (int i = 0; i < NCAND; i++) {
                if (used[i]) continue;
                float v = sval[i]; int ix = sidx[i];
                if (v > bv || (v == bv && ix < bi)) { bv = v; bi = ix; bp = i; }
            }
            used[bp] = true;
            g_topv[q * TOPK + j] = bv;
            g_topi[q * TOPK + j] = bi;
        }
    }
}

// ---------------------------------------------------------------------------
// Gather outputs (mask input is int32 — confirmed R1/R2)
// ---------------------------------------------------------------------------
__global__ __launch_bounds__(128) void gather_kernel(
    const int* __restrict__ tokens,
    const int* __restrict__ mask,
    const int* __restrict__ ids,
    const float* __restrict__ dk,
    float* __restrict__ out
) {
    const int item = blockIdx.x;
    const int tid = threadIdx.x;
    const int di = g_topi[item];

    out[OFF_TOK + (size_t)item * SDOC + tid] =
        (float)tokens[(size_t)di * SDOC + tid];
    out[OFF_MASK + (size_t)item * SDOC + tid] =
        mask[(size_t)di * SDOC + tid] ? 1.0f : 0.0f;

    const float* e = dk + (size_t)di * DIM;
    #pragma unroll
    for (int c = tid; c < DIM; c += 128)
        out[OFF_EMB + (size_t)item * DIM + c] = e[c];

    if (tid == 0) out[OFF_SCORE + item] = g_topv[item];
    if (tid == 1) out[OFF_IDS + item]   = (float)ids[di];
}

// ---------------------------------------------------------------------------
extern "C" void kernel_launch(void* const* d_in, const int* in_sizes, int n_in,
                              void* d_out, int out_size) {
    const float* qe   = (const float*)d_in[0];
    const float* dk   = (const float*)d_in[1];
    const int*   tok  = (const int*)d_in[2];
    const int*   mask = (const int*)d_in[3];
    const int*   ids  = (const int*)d_in[4];
    float* out = (float*)d_out;

    // pipeline (3*32KB) ∪ epilogue (128*130*4 + 512 = 67072) -> 96KB region
    const int dynsmem = NSLOT * STG_BYTES + 128;
    static int attr_done = 0;
    if (!attr_done) {
        cudaFuncSetAttribute(score_gemm_mma,
                             cudaFuncAttributeMaxDynamicSharedMemorySize, dynsmem);
        attr_done = 1;
    }

    qnorm_kernel<<<NQ, 256>>>(qe);
    docprep_kernel<<<NDPAD, 256>>>(dk);

    dim3 grid(4, NT);   // qtile fast-varying -> doc tile L2 reuse
    score_gemm_mma<<<grid, 128, dynsmem>>>();

    merge_kernel<<<NQ, 256>>>();
    rescore_kernel<<<NQ, 256>>>(dk);
    gather_kernel<<<NQ * TOPK, 128>>>(tok, mask, ids, dk, out);
}

// round 12
// speedup vs baseline: 1.5247x; 1.5247x over previous
#include <cuda_runtime.h>
#include <cuda_bf16.h>
#include <math.h>
#include <float.h>
#include <stdint.h>

// Problem constants
#define NQ 512
#define DIM 768
#define ND 100000
#define TOPK 8
#define SDOC 128

#define TILE_N 128
#define NT 782                    // ceil(100000/128)
#define NDPAD (NT * 128)          // 100096 (96 zero rows)
#define NC (NT * 8)               // 6256 candidates per query
#define NCAND 16                  // exact-rescore set size

#define KSTAGES 12                // K=768 in 64-wide stages
#define STG_A 16384               // 128 rows x 128B
#define STG_BYTES 32768           // A + B
#define NSLOT 3

// Output layout (fp32 concat, reference return order)
#define OFF_TOK   0u
#define OFF_MASK  524288u
#define OFF_SCORE 1048576u
#define OFF_IDS   1052672u
#define OFF_EMB   1056768u

typedef unsigned long long ull;

// Scratch (device globals)
__device__ float g_qn[NQ * DIM];
__device__ __align__(128) unsigned char g_qnT[4 * KSTAGES * STG_A];          // tiled queries
__device__ __align__(128) unsigned char g_dkT[(size_t)NT * KSTAGES * STG_A]; // 153.6MB tiled docs
__device__ float g_dinv[ND];
__device__ ull   g_ck[(size_t)NQ * NC];
__device__ int   g_cand[NQ * NCAND];
__device__ float g_topv[NQ * TOPK];
__device__ int   g_topi[NQ * TOPK];

// ---------------------------------------------------------------------------
// helpers
// ---------------------------------------------------------------------------
__device__ __forceinline__ uint32_t smem_u32(const void* p) {
    uint32_t a;
    asm("{ .reg .u64 t; cvta.to.shared.u64 t, %1; cvt.u32.u64 %0, t; }"
        : "=r"(a) : "l"(p));
    return a;
}
__device__ __forceinline__ uint64_t gmem_u64(const void* p) {
    uint64_t r;
    asm("cvta.to.global.u64 %0, %1;" : "=l"(r) : "l"(p));
    return r;
}
__device__ __forceinline__ uint32_t f2sort(float f) {
    uint32_t u = __float_as_uint(f);
    return (u & 0x80000000u) ? ~u : (u | 0x80000000u);
}
// tiled+swizzled byte offset of bf16 element c (0..767) of row (0..127)
__device__ __forceinline__ size_t tiled_off(int row, int c) {
    int stage = c >> 6;
    int cc = c & 63;
    int chunk = (cc >> 3) ^ (row & 7);
    return (size_t)stage * STG_A + (size_t)row * 128 + chunk * 16 + (cc & 7) * 2;
}

#define MBAR_INIT(a, c) \
    asm volatile("mbarrier.init.shared.b64 [%0], %1;" :: "r"(a), "r"(c) : "memory")
#define MBAR_EXPECT(a, n) \
    asm volatile("mbarrier.arrive.expect_tx.shared.b64 _, [%0], %1;" :: "r"(a), "r"(n) : "memory")
__device__ __forceinline__ void mbar_wait(uint32_t mbar, uint32_t parity) {
    asm volatile(
        "{\n\t.reg .pred P1;\n\t"
        "WAIT_LOOP_%=:\n\t"
        "mbarrier.try_wait.parity.acquire.cta.shared::cta.b64 P1, [%0], %1, 0x989680;\n\t"
        "@P1 bra.uni WAIT_DONE_%=;\n\t"
        "bra.uni WAIT_LOOP_%=;\n\t"
        "WAIT_DONE_%=:\n\t}"
        :: "r"(mbar), "r"(parity) : "memory");
}
__device__ __forceinline__ void bulk_cp(uint32_t dst, uint64_t src, uint32_t mbar) {
    asm volatile(
        "cp.async.bulk.shared::cluster.global.mbarrier::complete_tx::bytes "
        "[%0], [%1], %2, [%3];"
        :: "r"(dst), "l"(src), "r"(16384), "r"(mbar) : "memory");
}

#define LDSM4(r0,r1,r2,r3,a) \
    asm volatile("ldmatrix.sync.aligned.m8n8.x4.shared.b16 {%0,%1,%2,%3}, [%4];" \
                 : "=r"(r0),"=r"(r1),"=r"(r2),"=r"(r3) : "r"(a))

__device__ __forceinline__ void mma16816(float* c, uint32_t a0, uint32_t a1,
                                         uint32_t a2, uint32_t a3,
                                         uint32_t b0, uint32_t b1) {
    asm volatile(
        "mma.sync.aligned.m16n8k16.row.col.f32.bf16.bf16.f32 "
        "{%0,%1,%2,%3}, {%4,%5,%6,%7}, {%8,%9}, {%0,%1,%2,%3};"
        : "+f"(c[0]), "+f"(c[1]), "+f"(c[2]), "+f"(c[3])
        : "r"(a0), "r"(a1), "r"(a2), "r"(a3), "r"(b0), "r"(b1));
}

// ---------------------------------------------------------------------------
// Query normalize -> fp32 (for rescore) + tiled/swizzled bf16 (for GEMM)
// ---------------------------------------------------------------------------
__global__ __launch_bounds__(256) void qnorm_kernel(const float* __restrict__ q) {
    int r = blockIdx.x;
    __shared__ float red[256];
    __shared__ float s_inv;
    float v0 = q[r * DIM + threadIdx.x];
    float v1 = q[r * DIM + threadIdx.x + 256];
    float v2 = q[r * DIM + threadIdx.x + 512];
    red[threadIdx.x] = v0 * v0 + v1 * v1 + v2 * v2;
    __syncthreads();
    for (int st = 128; st >= 1; st >>= 1) {
        if (threadIdx.x < st) red[threadIdx.x] += red[threadIdx.x + st];
        __syncthreads();
    }
    if (threadIdx.x == 0) s_inv = 1.0f / fmaxf(sqrtf(red[0]), 1e-12f);
    __syncthreads();
    float inv = s_inv;
    int tile = r >> 7, row = r & 127;
    unsigned char* obase = g_qnT + (size_t)tile * KSTAGES * STG_A;
    #pragma unroll
    for (int e = 0; e < 3; e++) {
        int c = threadIdx.x + e * 256;
        float v = (e == 0 ? v0 : (e == 1 ? v1 : v2)) * inv;
        g_qn[r * DIM + c] = v;
        *(__nv_bfloat16*)(obase + tiled_off(row, c)) = __float2bfloat16(v);
    }
}

// ---------------------------------------------------------------------------
// Doc prep: norm + bf16 convert into tiled/swizzled layout (zero pad tail)
// ---------------------------------------------------------------------------
__global__ __launch_bounds__(256) void docprep_kernel(const float* __restrict__ dk) {
    int d = blockIdx.x;               // 0..NDPAD-1
    int tile = d >> 7, row = d & 127;
    unsigned char* obase = g_dkT + (size_t)tile * KSTAGES * STG_A;
    if (d >= ND) {
        #pragma unroll
        for (int e = 0; e < 3; e++) {
            int c = threadIdx.x + e * 256;
            *(__nv_bfloat16*)(obase + tiled_off(row, c)) = __float2bfloat16(0.f);
        }
        return;
    }
    const float* srow = dk + (size_t)d * DIM;
    float v0 = srow[threadIdx.x];
    float v1 = srow[threadIdx.x + 256];
    float v2 = srow[threadIdx.x + 512];
    __shared__ float red[256];
    __shared__ float s_inv;
    red[threadIdx.x] = v0 * v0 + v1 * v1 + v2 * v2;
    __syncthreads();
    for (int st = 128; st >= 1; st >>= 1) {
        if (threadIdx.x < st) red[threadIdx.x] += red[threadIdx.x + st];
        __syncthreads();
    }
    if (threadIdx.x == 0) {
        float inv = 1.0f / fmaxf(sqrtf(red[0]), 1e-12f);
        s_inv = inv;
        g_dinv[d] = inv;
    }
    __syncthreads();
    float inv = s_inv;
    #pragma unroll
    for (int e = 0; e < 3; e++) {
        int c = threadIdx.x + e * 256;
        float v = (e == 0 ? v0 : (e == 1 ? v1 : v2)) * inv;
        *(__nv_bfloat16*)(obase + tiled_off(row, c)) = __float2bfloat16(v);
    }
}

// ---------------------------------------------------------------------------
// Phase-1 GEMM: 128q x 128docs per CTA, 8 warps (warp tile 64x32),
// K=768 as 12 stages of 64, cp.async.bulk 3-slot mbarrier pipeline.
// Fused per-query top-8 candidate epilogue.
// ---------------------------------------------------------------------------
#define SCORE_LD 130

__global__ __launch_bounds__(256, 2) void score_gemm_mma() {
    extern __shared__ char dynsm[];
    __shared__ __align__(8) ull s_full[NSLOT];

    const int tid  = threadIdx.x;
    const int lane = tid & 31;
    const int wid  = tid >> 5;
    const int wm   = (wid & 1) * 64;   // warp M offset (2-way)
    const int wn   = (wid >> 1) * 32;  // warp N offset (4-way)
    const int qBase = blockIdx.x * 128;
    const int nBase = blockIdx.y * TILE_N;
    const int valid = min(TILE_N, ND - nBase);

    // 128-align the pipeline region
    const uint32_t raw = smem_u32(dynsm);
    const uint32_t smbase = (raw + 127u) & ~127u;
    char* bufp = dynsm + (smbase - raw);

    const uint64_t srcA = gmem_u64(g_qnT) + (size_t)blockIdx.x * KSTAGES * STG_A;
    const uint64_t srcB = gmem_u64(g_dkT) + (size_t)blockIdx.y * KSTAGES * STG_A;

    if (tid == 0) {
        #pragma unroll
        for (int i = 0; i < NSLOT; i++) MBAR_INIT(smem_u32(&s_full[i]), 1);
    }
    __syncthreads();

    #define ISSUE(s) do { \
        int _slot = (s) % NSLOT; \
        uint32_t _mb = smem_u32(&s_full[_slot]); \
        uint32_t _dst = smbase + _slot * STG_BYTES; \
        MBAR_EXPECT(_mb, STG_BYTES); \
        bulk_cp(_dst, srcA + (size_t)(s) * STG_A, _mb); \
        bulk_cp(_dst + STG_A, srcB + (size_t)(s) * STG_A, _mb); \
    } while (0)

    if (tid == 0) { ISSUE(0); ISSUE(1); ISSUE(2); }

    float acc[4][4][4];
    #pragma unroll
    for (int mi = 0; mi < 4; mi++)
        #pragma unroll
        for (int ni = 0; ni < 4; ni++)
            #pragma unroll
            for (int e = 0; e < 4; e++) acc[mi][ni][e] = 0.f;

    for (int s = 0; s < KSTAGES; s++) {
        const int slot = s % NSLOT;
        mbar_wait(smem_u32(&s_full[slot]), (s / NSLOT) & 1);
        const uint32_t buf = smbase + slot * STG_BYTES;

        #pragma unroll
        for (int kk = 0; kk < 4; kk++) {      // four K16 blocks per 64-elem stage
            uint32_t aF[4][4], bF[2][4];
            #pragma unroll
            for (int mi = 0; mi < 4; mi++) {
                int row = wm + mi * 16 + (lane & 15);
                int chunk = (kk * 2 + (lane >> 4)) ^ (lane & 7);
                LDSM4(aF[mi][0], aF[mi][1], aF[mi][2], aF[mi][3],
                      buf + row * 128 + chunk * 16);
            }
            #pragma unroll
            for (int nb = 0; nb < 2; nb++) {
                int m = lane >> 3;
                int row = wn + nb * 16 + (m >> 1) * 8 + (lane & 7);
                int chunk = (kk * 2 + (m & 1)) ^ (lane & 7);
                LDSM4(bF[nb][0], bF[nb][1], bF[nb][2], bF[nb][3],
                      buf + STG_A + row * 128 + chunk * 16);
            }
            #pragma unroll
            for (int mi = 0; mi < 4; mi++)
                #pragma unroll
                for (int n8 = 0; n8 < 4; n8++)
                    mma16816(acc[mi][n8],
                             aF[mi][0], aF[mi][1], aF[mi][2], aF[mi][3],
                             bF[n8 >> 1][(n8 & 1) * 2], bF[n8 >> 1][(n8 & 1) * 2 + 1]);
        }
        __syncthreads();
        if (tid == 0 && s + NSLOT < KSTAGES) ISSUE(s + NSLOT);
    }
    #undef ISSUE

    // --- epilogue: scores -> smem (reuse pipeline region), per-query top-8
    float* sc = (float*)bufp;           // [128][SCORE_LD]
    const int mrow = lane >> 2;
    const int ncol = (lane & 3) * 2;
    #pragma unroll
    for (int mi = 0; mi < 4; mi++) {
        #pragma unroll
        for (int n8 = 0; n8 < 4; n8++) {
            int m = wm + mi * 16 + mrow;
            int n = wn + n8 * 8 + ncol;
            *(float2*)&sc[m * SCORE_LD + n] = make_float2(acc[mi][n8][0], acc[mi][n8][1]);
            *(float2*)&sc[(m + 8) * SCORE_LD + n] = make_float2(acc[mi][n8][2], acc[mi][n8][3]);
        }
    }
    __syncthreads();

    // two threads per query, each scans 64 columns keeping top-8 keys
    const int q = tid >> 1;
    const int h = tid & 1;
    ull key[8];
    #pragma unroll
    for (int j = 0; j < 8; j++) key[j] = 0;
    for (int c = 0; c < 64; c++) {
        int col = h * 64 + c;
        if (col >= valid) break;
        float v = sc[q * SCORE_LD + col];
        ull k = ((ull)f2sort(v) << 32) | (uint32_t)(~(uint32_t)(nBase + col));
        if (k > key[7]) {
            bool placed = false;
            #pragma unroll
            for (int p = 7; p >= 0; p--) {
                bool upper = (p > 0) && (k > key[p - 1]);
                if (!placed) {
                    if (upper) key[p] = key[p - 1];
                    else       { key[p] = k; placed = true; }
                }
            }
        }
    }
    // partner exchange (lanes 2q, 2q+1 adjacent in same warp)
    ull pk[8];
    #pragma unroll
    for (int j = 0; j < 8; j++)
        pk[j] = __shfl_down_sync(0xFFFFFFFFu, key[j], 1);
    if (h == 0) {
        ull outk[8];
        int ia = 0, ib = 0;
        #pragma unroll
        for (int o = 0; o < 8; o++) {
            bool ta = (ib >= 8) || (ia < 8 && key[ia] >= pk[ib]);
            outk[o] = ta ? key[ia++] : pk[ib++];
        }
        size_t base = ((size_t)(qBase + q) * NT + blockIdx.y) * 8;
        #pragma unroll
        for (int j = 0; j < 8; j++) g_ck[base + j] = outk[j];
    }
}

// ---------------------------------------------------------------------------
// Merge: per query, tree-merge 6256 candidate keys -> top-16
// ---------------------------------------------------------------------------
__device__ __forceinline__ void merge16(ull* dst, const ull* a, const ull* b,
                                        int la, int lb) {
    int ia = 0, ib = 0;
    #pragma unroll
    for (int o = 0; o < 16; o++) {
        bool ta = (ib >= lb) || (ia < la && a[ia] >= b[ib]);
        dst[o] = ta ? a[ia++] : b[ib++];
    }
}

__global__ __launch_bounds__(256) void merge_kernel() {
    const int q = blockIdx.x;
    const int tid = threadIdx.x;
    __shared__ ull bufA[2048];
    __shared__ ull bufB[2048];

    ull loc[8];
    #pragma unroll
    for (int j = 0; j < 8; j++) loc[j] = 0;
    const ull* ck = g_ck + (size_t)q * NC;
    for (int i = tid; i < NC; i += 256) {
        ull k = ck[i];
        if (k > loc[7]) {
            bool placed = false;
            #pragma unroll
            for (int p = 7; p >= 0; p--) {
                bool upper = (p > 0) && (k > loc[p - 1]);
                if (!placed) {
                    if (upper) loc[p] = loc[p - 1];
                    else       { loc[p] = k; placed = true; }
                }
            }
        }
    }
    #pragma unroll
    for (int j = 0; j < 8; j++) bufA[tid * 8 + j] = loc[j];
    __syncthreads();

    if (tid < 128) merge16(&bufB[tid * 16], &bufA[2 * tid * 8], &bufA[(2 * tid + 1) * 8], 8, 8);
    __syncthreads();
    if (tid < 64) merge16(&bufA[tid * 16], &bufB[2 * tid * 16], &bufB[(2 * tid + 1) * 16], 16, 16);
    __syncthreads();
    if (tid < 32) merge16(&bufB[tid * 16], &bufA[2 * tid * 16], &bufA[(2 * tid + 1) * 16], 16, 16);
    __syncthreads();
    if (tid < 16) merge16(&bufA[tid * 16], &bufB[2 * tid * 16], &bufB[(2 * tid + 1) * 16], 16, 16);
    __syncthreads();
    if (tid < 8)  merge16(&bufB[tid * 16], &bufA[2 * tid * 16], &bufA[(2 * tid + 1) * 16], 16, 16);
    __syncthreads();
    if (tid < 4)  merge16(&bufA[tid * 16], &bufB[2 * tid * 16], &bufB[(2 * tid + 1) * 16], 16, 16);
    __syncthreads();
    if (tid < 2)  merge16(&bufB[tid * 16], &bufA[2 * tid * 16], &bufA[(2 * tid + 1) * 16], 16, 16);
    __syncthreads();
    if (tid < 1)  merge16(&bufA[0], &bufB[0], &bufB[16], 16, 16);
    __syncthreads();

    if (tid < NCAND)
        g_cand[q * NCAND + tid] = (int)(~(uint32_t)(bufA[tid] & 0xFFFFFFFFull));
}

// ---------------------------------------------------------------------------
// Exact fp32 rescore of 16 candidates + final top-8 (tie -> lower index)
// ---------------------------------------------------------------------------
__global__ __launch_bounds__(256) void rescore_kernel(const float* __restrict__ dk) {
    const int q = blockIdx.x;
    const int tid = threadIdx.x;
    const int wid = tid >> 5, lane = tid & 31;
    __shared__ float qrow[DIM];
    __shared__ float sval[NCAND];
    __shared__ int   sidx[NCAND];

    for (int i = tid; i < DIM; i += 256) qrow[i] = g_qn[q * DIM + i];
    __syncthreads();

    #pragma unroll
    for (int rep = 0; rep < 2; rep++) {
        int c = wid + rep * 8;
        int doc = g_cand[q * NCAND + c];
        const float* drow = dk + (size_t)doc * DIM;
        float s = 0.f;
        #pragma unroll
        for (int e = 0; e < DIM / 32; e++)
            s = fmaf(qrow[lane + e * 32], drow[lane + e * 32], s);
        #pragma unroll
        for (int off = 16; off >= 1; off >>= 1)
            s += __shfl_xor_sync(0xFFFFFFFFu, s, off);
        if (lane == 0) { sval[c] = s * g_dinv[doc]; sidx[c] = doc; }
    }
    __syncthreads();

    if (tid == 0) {
        bool used[NCAND];
        #pragma unroll
        for (int i = 0; i < NCAND; i++) used[i] = false;
        for (int j = 0; j < TOPK; j++) {
            float bv = -FLT_MAX; int bi = 0x7FFFFFFF; int bp = -1;
            for (int i = 0; i < NCAND; i++) {
                if (used[i]) continue;
                float v = sval[i]; int ix = sidx[i];
                if (v > bv || (v == bv && ix < bi)) { bv = v; bi = ix; bp = i; }
            }
            used[bp] = true;
            g_topv[q * TOPK + j] = bv;
            g_topi[q * TOPK + j] = bi;
        }
    }
}

// ---------------------------------------------------------------------------
// Gather outputs (mask input is int32 — confirmed R1/R2)
// ---------------------------------------------------------------------------
__global__ __launch_bounds__(128) void gather_kernel(
    const int* __restrict__ tokens,
    const int* __restrict__ mask,
    const int* __restrict__ ids,
    const float* __restrict__ dk,
    float* __restrict__ out
) {
    const int item = blockIdx.x;
    const int tid = threadIdx.x;
    const int di = g_topi[item];

    out[OFF_TOK + (size_t)item * SDOC + tid] =
        (float)tokens[(size_t)di * SDOC + tid];
    out[OFF_MASK + (size_t)item * SDOC + tid] =
        mask[(size_t)di * SDOC + tid] ? 1.0f : 0.0f;

    const float* e = dk + (size_t)di * DIM;
    #pragma unroll
    for (int c = tid; c < DIM; c += 128)
        out[OFF_EMB + (size_t)item * DIM + c] = e[c];

    if (tid == 0) out[OFF_SCORE + item] = g_topv[item];
    if (tid == 1) out[OFF_IDS + item]   = (float)ids[di];
}

// ---------------------------------------------------------------------------
extern "C" void kernel_launch(void* const* d_in, const int* in_sizes, int n_in,
                              void* d_out, int out_size) {
    const float* qe   = (const float*)d_in[0];
    const float* dk   = (const float*)d_in[1];
    const int*   tok  = (const int*)d_in[2];
    const int*   mask = (const int*)d_in[3];
    const int*   ids  = (const int*)d_in[4];
    float* out = (float*)d_out;

    // pipeline (3*32KB) and score tile (128*130*4=66.5KB) share the region
    const int dynsmem = NSLOT * STG_BYTES + 128;
    static int attr_done = 0;
    if (!attr_done) {
        cudaFuncSetAttribute(score_gemm_mma,
                             cudaFuncAttributeMaxDynamicSharedMemorySize, dynsmem);
        attr_done = 1;
    }

    qnorm_kernel<<<NQ, 256>>>(qe);
    docprep_kernel<<<NDPAD, 256>>>(dk);

    dim3 grid(4, NT);   // qtile fast-varying -> doc tile L2 reuse
    score_gemm_mma<<<grid, 256, dynsmem>>>();

    merge_kernel<<<NQ, 256>>>();
    rescore_kernel<<<NQ, 256>>>(dk);
    gather_kernel<<<NQ * TOPK, 128>>>(tok, mask, ids, dk, out);
}

// round 13
// speedup vs baseline: 1.7725x; 1.1625x over previous
#include <cuda_runtime.h>
#include <cuda_bf16.h>
#include <math.h>
#include <float.h>
#include <stdint.h>

// Problem constants
#define NQ 512
#define DIM 768
#define ND 100000
#define TOPK 8
#define SDOC 128

#define TILE_M 64                 // queries per CTA
#define TILE_N 128                // docs per CTA
#define NQT 8                     // 512/64 query tiles
#define NT 782                    // ceil(100000/128)
#define NDPAD (NT * 128)
#define CPT 4                     // candidates kept per (query, tile)
#define NC (NT * CPT)             // 3128 candidates per query
#define NCAND 16                  // exact-rescore set size

#define KSTAGES 12                // K=768 in 64-wide stages
#define A_STG 8192                // 64 rows x 128B
#define B_STG 16384               // 128 rows x 128B
#define STG_BYTES (A_STG + B_STG) // 24KB per stage
#define NSLOT 3

// Output layout (fp32 concat, reference return order)
#define OFF_TOK   0u
#define OFF_MASK  524288u
#define OFF_SCORE 1048576u
#define OFF_IDS   1052672u
#define OFF_EMB   1056768u

typedef unsigned long long ull;

// Scratch (device globals)
__device__ float g_qn[NQ * DIM];
__device__ __align__(128) unsigned char g_qnT[NQT * KSTAGES * A_STG];        // tiled queries
__device__ __align__(128) unsigned char g_dkT[(size_t)NT * KSTAGES * B_STG]; // 153.6MB tiled docs
__device__ float g_dinv[ND];
__device__ ull   g_ck[(size_t)NQ * NC];
__device__ int   g_cand[NQ * NCAND];
__device__ float g_topv[NQ * TOPK];
__device__ int   g_topi[NQ * TOPK];

// ---------------------------------------------------------------------------
// helpers
// ---------------------------------------------------------------------------
__device__ __forceinline__ uint32_t smem_u32(const void* p) {
    uint32_t a;
    asm("{ .reg .u64 t; cvta.to.shared.u64 t, %1; cvt.u32.u64 %0, t; }"
        : "=r"(a) : "l"(p));
    return a;
}
__device__ __forceinline__ uint64_t gmem_u64(const void* p) {
    uint64_t r;
    asm("cvta.to.global.u64 %0, %1;" : "=l"(r) : "l"(p));
    return r;
}
__device__ __forceinline__ uint32_t f2sort(float f) {
    uint32_t u = __float_as_uint(f);
    return (u & 0x80000000u) ? ~u : (u | 0x80000000u);
}
// tiled+swizzled byte offset of bf16 element c (0..767), A tiles (64 rows)
__device__ __forceinline__ size_t tiled_off_a(int row, int c) {
    int stage = c >> 6;
    int cc = c & 63;
    int chunk = (cc >> 3) ^ (row & 7);
    return (size_t)stage * A_STG + (size_t)row * 128 + chunk * 16 + (cc & 7) * 2;
}
// B tiles (128 rows)
__device__ __forceinline__ size_t tiled_off_b(int row, int c) {
    int stage = c >> 6;
    int cc = c & 63;
    int chunk = (cc >> 3) ^ (row & 7);
    return (size_t)stage * B_STG + (size_t)row * 128 + chunk * 16 + (cc & 7) * 2;
}

#define MBAR_INIT(a, c) \
    asm volatile("mbarrier.init.shared.b64 [%0], %1;" :: "r"(a), "r"(c) : "memory")
#define MBAR_EXPECT(a, n) \
    asm volatile("mbarrier.arrive.expect_tx.shared.b64 _, [%0], %1;" :: "r"(a), "r"(n) : "memory")
__device__ __forceinline__ void mbar_wait(uint32_t mbar, uint32_t parity) {
    asm volatile(
        "{\n\t.reg .pred P1;\n\t"
        "WAIT_LOOP_%=:\n\t"
        "mbarrier.try_wait.parity.acquire.cta.shared::cta.b64 P1, [%0], %1, 0x989680;\n\t"
        "@P1 bra.uni WAIT_DONE_%=;\n\t"
        "bra.uni WAIT_LOOP_%=;\n\t"
        "WAIT_DONE_%=:\n\t}"
        :: "r"(mbar), "r"(parity) : "memory");
}
__device__ __forceinline__ void bulk_cp(uint32_t dst, uint64_t src, uint32_t bytes,
                                        uint32_t mbar) {
    asm volatile(
        "cp.async.bulk.shared::cluster.global.mbarrier::complete_tx::bytes "
        "[%0], [%1], %2, [%3];"
        :: "r"(dst), "l"(src), "r"(bytes), "r"(mbar) : "memory");
}

#define LDSM4(r0,r1,r2,r3,a) \
    asm volatile("ldmatrix.sync.aligned.m8n8.x4.shared.b16 {%0,%1,%2,%3}, [%4];" \
                 : "=r"(r0),"=r"(r1),"=r"(r2),"=r"(r3) : "r"(a))

__device__ __forceinline__ void mma16816(float* c, uint32_t a0, uint32_t a1,
                                         uint32_t a2, uint32_t a3,
                                         uint32_t b0, uint32_t b1) {
    asm volatile(
        "mma.sync.aligned.m16n8k16.row.col.f32.bf16.bf16.f32 "
        "{%0,%1,%2,%3}, {%4,%5,%6,%7}, {%8,%9}, {%0,%1,%2,%3};"
        : "+f"(c[0]), "+f"(c[1]), "+f"(c[2]), "+f"(c[3])
        : "r"(a0), "r"(a1), "r"(a2), "r"(a3), "r"(b0), "r"(b1));
}

// ---------------------------------------------------------------------------
// Query normalize -> fp32 (for rescore) + tiled/swizzled bf16 (for GEMM)
// ---------------------------------------------------------------------------
__global__ __launch_bounds__(256) void qnorm_kernel(const float* __restrict__ q) {
    int r = blockIdx.x;
    __shared__ float red[256];
    __shared__ float s_inv;
    float v0 = q[r * DIM + threadIdx.x];
    float v1 = q[r * DIM + threadIdx.x + 256];
    float v2 = q[r * DIM + threadIdx.x + 512];
    red[threadIdx.x] = v0 * v0 + v1 * v1 + v2 * v2;
    __syncthreads();
    for (int st = 128; st >= 1; st >>= 1) {
        if (threadIdx.x < st) red[threadIdx.x] += red[threadIdx.x + st];
        __syncthreads();
    }
    if (threadIdx.x == 0) s_inv = 1.0f / fmaxf(sqrtf(red[0]), 1e-12f);
    __syncthreads();
    float inv = s_inv;
    int tile = r >> 6, row = r & 63;
    unsigned char* obase = g_qnT + (size_t)tile * KSTAGES * A_STG;
    #pragma unroll
    for (int e = 0; e < 3; e++) {
        int c = threadIdx.x + e * 256;
        float v = (e == 0 ? v0 : (e == 1 ? v1 : v2)) * inv;
        g_qn[r * DIM + c] = v;
        *(__nv_bfloat16*)(obase + tiled_off_a(row, c)) = __float2bfloat16(v);
    }
}

// ---------------------------------------------------------------------------
// Doc prep: norm + bf16 convert into tiled/swizzled layout (zero pad tail)
// ---------------------------------------------------------------------------
__global__ __launch_bounds__(256) void docprep_kernel(const float* __restrict__ dk) {
    int d = blockIdx.x;               // 0..NDPAD-1
    int tile = d >> 7, row = d & 127;
    unsigned char* obase = g_dkT + (size_t)tile * KSTAGES * B_STG;
    if (d >= ND) {
        #pragma unroll
        for (int e = 0; e < 3; e++) {
            int c = threadIdx.x + e * 256;
            *(__nv_bfloat16*)(obase + tiled_off_b(row, c)) = __float2bfloat16(0.f);
        }
        return;
    }
    const float* srow = dk + (size_t)d * DIM;
    float v0 = srow[threadIdx.x];
    float v1 = srow[threadIdx.x + 256];
    float v2 = srow[threadIdx.x + 512];
    __shared__ float red[256];
    __shared__ float s_inv;
    red[threadIdx.x] = v0 * v0 + v1 * v1 + v2 * v2;
    __syncthreads();
    for (int st = 128; st >= 1; st >>= 1) {
        if (threadIdx.x < st) red[threadIdx.x] += red[threadIdx.x + st];
        __syncthreads();
    }
    if (threadIdx.x == 0) {
        float inv = 1.0f / fmaxf(sqrtf(red[0]), 1e-12f);
        s_inv = inv;
        g_dinv[d] = inv;
    }
    __syncthreads();
    float inv = s_inv;
    #pragma unroll
    for (int e = 0; e < 3; e++) {
        int c = threadIdx.x + e * 256;
        float v = (e == 0 ? v0 : (e == 1 ? v1 : v2)) * inv;
        *(__nv_bfloat16*)(obase + tiled_off_b(row, c)) = __float2bfloat16(v);
    }
}

// ---------------------------------------------------------------------------
// Phase-1 GEMM: 64q x 128docs per CTA, 4 warps (warp tile 32x64),
// K=768 as 12 stages of 64, cp.async.bulk 3-slot mbarrier pipeline,
// 3 CTAs/SM. Fused per-query top-4 candidate epilogue.
// ---------------------------------------------------------------------------
#define SCORE_LD 130

__global__ __launch_bounds__(128, 3) void score_gemm_mma() {
    extern __shared__ char dynsm[];
    __shared__ __align__(8) ull s_full[NSLOT];

    const int tid  = threadIdx.x;
    const int lane = tid & 31;
    const int wid  = tid >> 5;
    const int wm   = (wid & 1) * 32;   // warp M offset (2-way)
    const int wn   = (wid >> 1) * 64;  // warp N offset (2-way)
    const int qBase = blockIdx.x * TILE_M;
    const int nBase = blockIdx.y * TILE_N;
    const int valid = min(TILE_N, ND - nBase);

    const uint32_t raw = smem_u32(dynsm);
    const uint32_t smbase = (raw + 127u) & ~127u;
    char* bufp = dynsm + (smbase - raw);

    const uint64_t srcA = gmem_u64(g_qnT) + (size_t)blockIdx.x * KSTAGES * A_STG;
    const uint64_t srcB = gmem_u64(g_dkT) + (size_t)blockIdx.y * KSTAGES * B_STG;

    if (tid == 0) {
        #pragma unroll
        for (int i = 0; i < NSLOT; i++) MBAR_INIT(smem_u32(&s_full[i]), 1);
    }
    __syncthreads();

    #define ISSUE(s) do { \
        int _slot = (s) % NSLOT; \
        uint32_t _mb = smem_u32(&s_full[_slot]); \
        uint32_t _dst = smbase + _slot * STG_BYTES; \
        MBAR_EXPECT(_mb, STG_BYTES); \
        bulk_cp(_dst, srcA + (size_t)(s) * A_STG, A_STG, _mb); \
        bulk_cp(_dst + A_STG, srcB + (size_t)(s) * B_STG, B_STG, _mb); \
    } while (0)

    if (tid == 0) { ISSUE(0); ISSUE(1); ISSUE(2); }

    float acc[2][8][4];
    #pragma unroll
    for (int mi = 0; mi < 2; mi++)
        #pragma unroll
        for (int ni = 0; ni < 8; ni++)
            #pragma unroll
            for (int e = 0; e < 4; e++) acc[mi][ni][e] = 0.f;

    for (int s = 0; s < KSTAGES; s++) {
        const int slot = s % NSLOT;
        mbar_wait(smem_u32(&s_full[slot]), (s / NSLOT) & 1);
        const uint32_t buf = smbase + slot * STG_BYTES;

        #pragma unroll
        for (int kk = 0; kk < 4; kk++) {      // four K16 blocks per 64-elem stage
            uint32_t aF[2][4], bF[4][4];
            #pragma unroll
            for (int mi = 0; mi < 2; mi++) {
                int row = wm + mi * 16 + (lane & 15);
                int chunk = (kk * 2 + (lane >> 4)) ^ (lane & 7);
                LDSM4(aF[mi][0], aF[mi][1], aF[mi][2], aF[mi][3],
                      buf + row * 128 + chunk * 16);
            }
            #pragma unroll
            for (int nb = 0; nb < 4; nb++) {
                int m = lane >> 3;
                int row = wn + nb * 16 + (m >> 1) * 8 + (lane & 7);
                int chunk = (kk * 2 + (m & 1)) ^ (lane & 7);
                LDSM4(bF[nb][0], bF[nb][1], bF[nb][2], bF[nb][3],
                      buf + A_STG + row * 128 + chunk * 16);
            }
            #pragma unroll
            for (int mi = 0; mi < 2; mi++)
                #pragma unroll
                for (int n8 = 0; n8 < 8; n8++)
                    mma16816(acc[mi][n8],
                             aF[mi][0], aF[mi][1], aF[mi][2], aF[mi][3],
                             bF[n8 >> 1][(n8 & 1) * 2], bF[n8 >> 1][(n8 & 1) * 2 + 1]);
        }
        __syncthreads();
        if (tid == 0 && s + NSLOT < KSTAGES) ISSUE(s + NSLOT);
    }
    #undef ISSUE

    // --- epilogue: scores -> smem (reuse pipeline region), per-query top-4
    float* sc = (float*)bufp;           // [64][SCORE_LD] = 33.3KB
    const int mrow = lane >> 2;
    const int ncol = (lane & 3) * 2;
    #pragma unroll
    for (int mi = 0; mi < 2; mi++) {
        #pragma unroll
        for (int n8 = 0; n8 < 8; n8++) {
            int m = wm + mi * 16 + mrow;
            int n = wn + n8 * 8 + ncol;
            *(float2*)&sc[m * SCORE_LD + n] = make_float2(acc[mi][n8][0], acc[mi][n8][1]);
            *(float2*)&sc[(m + 8) * SCORE_LD + n] = make_float2(acc[mi][n8][2], acc[mi][n8][3]);
        }
    }
    __syncthreads();

    // two threads per query, each scans 64 columns keeping top-4 keys
    const int q = tid >> 1;
    const int h = tid & 1;
    ull key[CPT];
    #pragma unroll
    for (int j = 0; j < CPT; j++) key[j] = 0;
    for (int c = 0; c < 64; c++) {
        int col = h * 64 + c;
        if (col >= valid) break;
        float v = sc[q * SCORE_LD + col];
        ull k = ((ull)f2sort(v) << 32) | (uint32_t)(~(uint32_t)(nBase + col));
        if (k > key[CPT - 1]) {
            bool placed = false;
            #pragma unroll
            for (int p = CPT - 1; p >= 0; p--) {
                bool upper = (p > 0) && (k > key[p - 1]);
                if (!placed) {
                    if (upper) key[p] = key[p - 1];
                    else       { key[p] = k; placed = true; }
                }
            }
        }
    }
    // partner exchange (lanes 2q, 2q+1 adjacent in same warp)
    ull pk[CPT];
    #pragma unroll
    for (int j = 0; j < CPT; j++)
        pk[j] = __shfl_down_sync(0xFFFFFFFFu, key[j], 1);
    if (h == 0) {
        ull outk[CPT];
        int ia = 0, ib = 0;
        #pragma unroll
        for (int o = 0; o < CPT; o++) {
            bool ta = (ib >= CPT) || (ia < CPT && key[ia] >= pk[ib]);
            outk[o] = ta ? key[ia++] : pk[ib++];
        }
        size_t base = ((size_t)(qBase + q) * NT + blockIdx.y) * CPT;
        #pragma unroll
        for (int j = 0; j < CPT; j++) g_ck[base + j] = outk[j];
    }
}

// ---------------------------------------------------------------------------
// Merge: per query, tree-merge 3128 candidate keys -> top-16
// ---------------------------------------------------------------------------
__device__ __forceinline__ void merge16(ull* dst, const ull* a, const ull* b,
                                        int la, int lb) {
    int ia = 0, ib = 0;
    #pragma unroll
    for (int o = 0; o < 16; o++) {
        bool ta = (ib >= lb) || (ia < la && a[ia] >= b[ib]);
        dst[o] = ta ? a[ia++] : b[ib++];
    }
}

__global__ __launch_bounds__(256) void merge_kernel() {
    const int q = blockIdx.x;
    const int tid = threadIdx.x;
    __shared__ ull bufA[2048];
    __shared__ ull bufB[2048];

    ull loc[8];
    #pragma unroll
    for (int j = 0; j < 8; j++) loc[j] = 0;
    const ull* ck = g_ck + (size_t)q * NC;
    for (int i = tid; i < NC; i += 256) {
        ull k = ck[i];
        if (k > loc[7]) {
            bool placed = false;
            #pragma unroll
            for (int p = 7; p >= 0; p--) {
                bool upper = (p > 0) && (k > loc[p - 1]);
                if (!placed) {
                    if (upper) loc[p] = loc[p - 1];
                    else       { loc[p] = k; placed = true; }
                }
            }
        }
    }
    #pragma unroll
    for (int j = 0; j < 8; j++) bufA[tid * 8 + j] = loc[j];
    __syncthreads();

    if (tid < 128) merge16(&bufB[tid * 16], &bufA[2 * tid * 8], &bufA[(2 * tid + 1) * 8], 8, 8);
    __syncthreads();
    if (tid < 64) merge16(&bufA[tid * 16], &bufB[2 * tid * 16], &bufB[(2 * tid + 1) * 16], 16, 16);
    __syncthreads();
    if (tid < 32) merge16(&bufB[tid * 16], &bufA[2 * tid * 16], &bufA[(2 * tid + 1) * 16], 16, 16);
    __syncthreads();
    if (tid < 16) merge16(&bufA[tid * 16], &bufB[2 * tid * 16], &bufB[(2 * tid + 1) * 16], 16, 16);
    __syncthreads();
    if (tid < 8)  merge16(&bufB[tid * 16], &bufA[2 * tid * 16], &bufA[(2 * tid + 1) * 16], 16, 16);
    __syncthreads();
    if (tid < 4)  merge16(&bufA[tid * 16], &bufB[2 * tid * 16], &bufB[(2 * tid + 1) * 16], 16, 16);
    __syncthreads();
    if (tid < 2)  merge16(&bufB[tid * 16], &bufA[2 * tid * 16], &bufA[(2 * tid + 1) * 16], 16, 16);
    __syncthreads();
    if (tid < 1)  merge16(&bufA[0], &bufB[0], &bufB[16], 16, 16);
    __syncthreads();

    if (tid < NCAND)
        g_cand[q * NCAND + tid] = (int)(~(uint32_t)(bufA[tid] & 0xFFFFFFFFull));
}

// ---------------------------------------------------------------------------
// Exact fp32 rescore of 16 candidates + final top-8 (tie -> lower index)
// ---------------------------------------------------------------------------
__global__ __launch_bounds__(256) void rescore_kernel(const float* __restrict__ dk) {
    const int q = blockIdx.x;
    const int tid = threadIdx.x;
    const int wid = tid >> 5, lane = tid & 31;
    __shared__ float qrow[DIM];
    __shared__ float sval[NCAND];
    __shared__ int   sidx[NCAND];

    for (int i = tid; i < DIM; i += 256) qrow[i] = g_qn[q * DIM + i];
    __syncthreads();

    #pragma unroll
    for (int rep = 0; rep < 2; rep++) {
        int c = wid + rep * 8;
        int doc = g_cand[q * NCAND + c];
        const float* drow = dk + (size_t)doc * DIM;
        float s = 0.f;
        #pragma unroll
        for (int e = 0; e < DIM / 32; e++)
            s = fmaf(qrow[lane + e * 32], drow[lane + e * 32], s);
        #pragma unroll
        for (int off = 16; off >= 1; off >>= 1)
            s += __shfl_xor_sync(0xFFFFFFFFu, s, off);
        if (lane == 0) { sval[c] = s * g_dinv[doc]; sidx[c] = doc; }
    }
    __syncthreads();

    if (tid == 0) {
        bool used[NCAND];
        #pragma unroll
        for (int i = 0; i < NCAND; i++) used[i] = false;
        for (int j = 0; j < TOPK; j++) {
            float bv = -FLT_MAX; int bi = 0x7FFFFFFF; int bp = -1;
            for (int i = 0; i < NCAND; i++) {
                if (used[i]) continue;
                float v = sval[i]; int ix = sidx[i];
                if (v > bv || (v == bv && ix < bi)) { bv = v; bi = ix; bp = i; }
            }
            used[bp] = true;
            g_topv[q * TOPK + j] = bv;
            g_topi[q * TOPK + j] = bi;
        }
    }
}

// ---------------------------------------------------------------------------
// Gather outputs (mask input is int32 — confirmed R1/R2)
// ---------------------------------------------------------------------------
__global__ __launch_bounds__(128) void gather_kernel(
    const int* __restrict__ tokens,
    const int* __restrict__ mask,
    const int* __restrict__ ids,
    const float* __restrict__ dk,
    float* __restrict__ out
) {
    const int item = blockIdx.x;
    const int tid = threadIdx.x;
    const int di = g_topi[item];

    out[OFF_TOK + (size_t)item * SDOC + tid] =
        (float)tokens[(size_t)di * SDOC + tid];
    out[OFF_MASK + (size_t)item * SDOC + tid] =
        mask[(size_t)di * SDOC + tid] ? 1.0f : 0.0f;

    const float* e = dk + (size_t)di * DIM;
    #pragma unroll
    for (int c = tid; c < DIM; c += 128)
        out[OFF_EMB + (size_t)item * DIM + c] = e[c];

    if (tid == 0) out[OFF_SCORE + item] = g_topv[item];
    if (tid == 1) out[OFF_IDS + item]   = (float)ids[di];
}

// ---------------------------------------------------------------------------
extern "C" void kernel_launch(void* const* d_in, const int* in_sizes, int n_in,
                              void* d_out, int out_size) {
    const float* qe   = (const float*)d_in[0];
    const float* dk   = (const float*)d_in[1];
    const int*   tok  = (const int*)d_in[2];
    const int*   mask = (const int*)d_in[3];
    const int*   ids  = (const int*)d_in[4];
    float* out = (float*)d_out;

    // pipeline (3*24KB) also hosts the 64x130 fp32 score tile (33.3KB)
    const int dynsmem = NSLOT * STG_BYTES + 128;   // 73856 -> 3 CTAs/SM
    static int attr_done = 0;
    if (!attr_done) {
        cudaFuncSetAttribute(score_gemm_mma,
                             cudaFuncAttributeMaxDynamicSharedMemorySize, dynsmem);
        attr_done = 1;
    }

    qnorm_kernel<<<NQ, 256>>>(qe);
    docprep_kernel<<<NDPAD, 256>>>(dk);

    dim3 grid(NQT, NT);   // qtile fast-varying -> doc tile L2 reuse (8x)
    score_gemm_mma<<<grid, 128, dynsmem>>>();

    merge_kernel<<<NQ, 256>>>();
    rescore_kernel<<<NQ, 256>>>(dk);
    gather_kernel<<<NQ * TOPK, 128>>>(tok, mask, ids, dk, out);
}

// round 14
// speedup vs baseline: 1.8078x; 1.0200x over previous
#include <cuda_runtime.h>
#include <cuda_bf16.h>
#include <math.h>
#include <float.h>
#include <stdint.h>

// Problem constants
#define NQ 512
#define DIM 768
#define ND 100000
#define TOPK 8
#define SDOC 128

#define TILE_M 64                 // queries per CTA
#define TILE_N 128                // docs per CTA
#define NQT 8                     // 512/64 query tiles
#define NT 782                    // ceil(100000/128)
#define NDPAD (NT * 128)
#define CPT 4                     // candidates kept per (query, tile)
#define NC (NT * CPT)             // 3128 candidates per query
#define NCAND 16                  // exact-rescore set size

#define KSTAGES 12                // K=768 in 64-wide stages
#define A_STG 8192                // 64 rows x 128B
#define B_STG 16384               // 128 rows x 128B
#define STG_BYTES (A_STG + B_STG) // 24KB per stage
#define NSLOT 3

// Output layout (fp32 concat, reference return order)
#define OFF_TOK   0u
#define OFF_MASK  524288u
#define OFF_SCORE 1048576u
#define OFF_IDS   1052672u
#define OFF_EMB   1056768u

typedef unsigned long long ull;

// Scratch (device globals)
__device__ float g_qn[NQ * DIM];
__device__ __align__(128) unsigned char g_qnT[NQT * KSTAGES * A_STG];        // tiled queries
__device__ __align__(128) unsigned char g_dkT[(size_t)NT * KSTAGES * B_STG]; // 153.6MB tiled docs
__device__ float g_dinv[ND];
__device__ ull   g_ck[(size_t)NQ * NC];

// ---------------------------------------------------------------------------
// helpers
// ---------------------------------------------------------------------------
__device__ __forceinline__ uint32_t smem_u32(const void* p) {
    uint32_t a;
    asm("{ .reg .u64 t; cvta.to.shared.u64 t, %1; cvt.u32.u64 %0, t; }"
        : "=r"(a) : "l"(p));
    return a;
}
__device__ __forceinline__ uint64_t gmem_u64(const void* p) {
    uint64_t r;
    asm("cvta.to.global.u64 %0, %1;" : "=l"(r) : "l"(p));
    return r;
}
__device__ __forceinline__ uint32_t f2sort(float f) {
    uint32_t u = __float_as_uint(f);
    return (u & 0x80000000u) ? ~u : (u | 0x80000000u);
}
// tiled+swizzled byte offset of bf16 element c (0..767), A tiles (64 rows)
__device__ __forceinline__ size_t tiled_off_a(int row, int c) {
    int stage = c >> 6;
    int cc = c & 63;
    int chunk = (cc >> 3) ^ (row & 7);
    return (size_t)stage * A_STG + (size_t)row * 128 + chunk * 16 + (cc & 7) * 2;
}
// B tiles (128 rows)
__device__ __forceinline__ size_t tiled_off_b(int row, int c) {
    int stage = c >> 6;
    int cc = c & 63;
    int chunk = (cc >> 3) ^ (row & 7);
    return (size_t)stage * B_STG + (size_t)row * 128 + chunk * 16 + (cc & 7) * 2;
}

#define MBAR_INIT(a, c) \
    asm volatile("mbarrier.init.shared.b64 [%0], %1;" :: "r"(a), "r"(c) : "memory")
#define MBAR_EXPECT(a, n) \
    asm volatile("mbarrier.arrive.expect_tx.shared.b64 _, [%0], %1;" :: "r"(a), "r"(n) : "memory")
__device__ __forceinline__ void mbar_wait(uint32_t mbar, uint32_t parity) {
    asm volatile(
        "{\n\t.reg .pred P1;\n\t"
        "WAIT_LOOP_%=:\n\t"
        "mbarrier.try_wait.parity.acquire.cta.shared::cta.b64 P1, [%0], %1, 0x989680;\n\t"
        "@P1 bra.uni WAIT_DONE_%=;\n\t"
        "bra.uni WAIT_LOOP_%=;\n\t"
        "WAIT_DONE_%=:\n\t}"
        :: "r"(mbar), "r"(parity) : "memory");
}
__device__ __forceinline__ void bulk_cp(uint32_t dst, uint64_t src, uint32_t bytes,
                                        uint32_t mbar) {
    asm volatile(
        "cp.async.bulk.shared::cluster.global.mbarrier::complete_tx::bytes "
        "[%0], [%1], %2, [%3];"
        :: "r"(dst), "l"(src), "r"(bytes), "r"(mbar) : "memory");
}

#define LDSM4(r0,r1,r2,r3,a) \
    asm volatile("ldmatrix.sync.aligned.m8n8.x4.shared.b16 {%0,%1,%2,%3}, [%4];" \
                 : "=r"(r0),"=r"(r1),"=r"(r2),"=r"(r3) : "r"(a))

__device__ __forceinline__ void mma16816(float* c, uint32_t a0, uint32_t a1,
                                         uint32_t a2, uint32_t a3,
                                         uint32_t b0, uint32_t b1) {
    asm volatile(
        "mma.sync.aligned.m16n8k16.row.col.f32.bf16.bf16.f32 "
        "{%0,%1,%2,%3}, {%4,%5,%6,%7}, {%8,%9}, {%0,%1,%2,%3};"
        : "+f"(c[0]), "+f"(c[1]), "+f"(c[2]), "+f"(c[3])
        : "r"(a0), "r"(a1), "r"(a2), "r"(a3), "r"(b0), "r"(b1));
}

// ---------------------------------------------------------------------------
// Query normalize -> fp32 (for rescore) + tiled/swizzled bf16 (for GEMM)
// ---------------------------------------------------------------------------
__global__ __launch_bounds__(256) void qnorm_kernel(const float* __restrict__ q) {
    int r = blockIdx.x;
    __shared__ float red[256];
    __shared__ float s_inv;
    float v0 = q[r * DIM + threadIdx.x];
    float v1 = q[r * DIM + threadIdx.x + 256];
    float v2 = q[r * DIM + threadIdx.x + 512];
    red[threadIdx.x] = v0 * v0 + v1 * v1 + v2 * v2;
    __syncthreads();
    for (int st = 128; st >= 1; st >>= 1) {
        if (threadIdx.x < st) red[threadIdx.x] += red[threadIdx.x + st];
        __syncthreads();
    }
    if (threadIdx.x == 0) s_inv = 1.0f / fmaxf(sqrtf(red[0]), 1e-12f);
    __syncthreads();
    float inv = s_inv;
    int tile = r >> 6, row = r & 63;
    unsigned char* obase = g_qnT + (size_t)tile * KSTAGES * A_STG;
    #pragma unroll
    for (int e = 0; e < 3; e++) {
        int c = threadIdx.x + e * 256;
        float v = (e == 0 ? v0 : (e == 1 ? v1 : v2)) * inv;
        g_qn[r * DIM + c] = v;
        *(__nv_bfloat16*)(obase + tiled_off_a(row, c)) = __float2bfloat16(v);
    }
}

// ---------------------------------------------------------------------------
// Doc prep: norm + bf16 convert into tiled/swizzled layout (zero pad tail)
// ---------------------------------------------------------------------------
__global__ __launch_bounds__(256) void docprep_kernel(const float* __restrict__ dk) {
    int d = blockIdx.x;               // 0..NDPAD-1
    int tile = d >> 7, row = d & 127;
    unsigned char* obase = g_dkT + (size_t)tile * KSTAGES * B_STG;
    if (d >= ND) {
        #pragma unroll
        for (int e = 0; e < 3; e++) {
            int c = threadIdx.x + e * 256;
            *(__nv_bfloat16*)(obase + tiled_off_b(row, c)) = __float2bfloat16(0.f);
        }
        return;
    }
    const float* srow = dk + (size_t)d * DIM;
    float v0 = srow[threadIdx.x];
    float v1 = srow[threadIdx.x + 256];
    float v2 = srow[threadIdx.x + 512];
    __shared__ float red[256];
    __shared__ float s_inv;
    red[threadIdx.x] = v0 * v0 + v1 * v1 + v2 * v2;
    __syncthreads();
    for (int st = 128; st >= 1; st >>= 1) {
        if (threadIdx.x < st) red[threadIdx.x] += red[threadIdx.x + st];
        __syncthreads();
    }
    if (threadIdx.x == 0) {
        float inv = 1.0f / fmaxf(sqrtf(red[0]), 1e-12f);
        s_inv = inv;
        g_dinv[d] = inv;
    }
    __syncthreads();
    float inv = s_inv;
    #pragma unroll
    for (int e = 0; e < 3; e++) {
        int c = threadIdx.x + e * 256;
        float v = (e == 0 ? v0 : (e == 1 ? v1 : v2)) * inv;
        *(__nv_bfloat16*)(obase + tiled_off_b(row, c)) = __float2bfloat16(v);
    }
}

// ---------------------------------------------------------------------------
// Phase-1 GEMM: 64q x 128docs per CTA, 4 warps (warp tile 32x64),
// K=768 as 12 stages of 64, cp.async.bulk 3-slot mbarrier pipeline,
// 3 CTAs/SM. Fused per-query top-4 candidate epilogue.
// (UNCHANGED from R13 — measured at the legacy-HMMA engine floor.)
// ---------------------------------------------------------------------------
#define SCORE_LD 130

__global__ __launch_bounds__(128, 3) void score_gemm_mma() {
    extern __shared__ char dynsm[];
    __shared__ __align__(8) ull s_full[NSLOT];

    const int tid  = threadIdx.x;
    const int lane = tid & 31;
    const int wid  = tid >> 5;
    const int wm   = (wid & 1) * 32;   // warp M offset (2-way)
    const int wn   = (wid >> 1) * 64;  // warp N offset (2-way)
    const int qBase = blockIdx.x * TILE_M;
    const int nBase = blockIdx.y * TILE_N;
    const int valid = min(TILE_N, ND - nBase);

    const uint32_t raw = smem_u32(dynsm);
    const uint32_t smbase = (raw + 127u) & ~127u;
    char* bufp = dynsm + (smbase - raw);

    const uint64_t srcA = gmem_u64(g_qnT) + (size_t)blockIdx.x * KSTAGES * A_STG;
    const uint64_t srcB = gmem_u64(g_dkT) + (size_t)blockIdx.y * KSTAGES * B_STG;

    if (tid == 0) {
        #pragma unroll
        for (int i = 0; i < NSLOT; i++) MBAR_INIT(smem_u32(&s_full[i]), 1);
    }
    __syncthreads();

    #define ISSUE(s) do { \
        int _slot = (s) % NSLOT; \
        uint32_t _mb = smem_u32(&s_full[_slot]); \
        uint32_t _dst = smbase + _slot * STG_BYTES; \
        MBAR_EXPECT(_mb, STG_BYTES); \
        bulk_cp(_dst, srcA + (size_t)(s) * A_STG, A_STG, _mb); \
        bulk_cp(_dst + A_STG, srcB + (size_t)(s) * B_STG, B_STG, _mb); \
    } while (0)

    if (tid == 0) { ISSUE(0); ISSUE(1); ISSUE(2); }

    float acc[2][8][4];
    #pragma unroll
    for (int mi = 0; mi < 2; mi++)
        #pragma unroll
        for (int ni = 0; ni < 8; ni++)
            #pragma unroll
            for (int e = 0; e < 4; e++) acc[mi][ni][e] = 0.f;

    for (int s = 0; s < KSTAGES; s++) {
        const int slot = s % NSLOT;
        mbar_wait(smem_u32(&s_full[slot]), (s / NSLOT) & 1);
        const uint32_t buf = smbase + slot * STG_BYTES;

        #pragma unroll
        for (int kk = 0; kk < 4; kk++) {      // four K16 blocks per 64-elem stage
            uint32_t aF[2][4], bF[4][4];
            #pragma unroll
            for (int mi = 0; mi < 2; mi++) {
                int row = wm + mi * 16 + (lane & 15);
                int chunk = (kk * 2 + (lane >> 4)) ^ (lane & 7);
                LDSM4(aF[mi][0], aF[mi][1], aF[mi][2], aF[mi][3],
                      buf + row * 128 + chunk * 16);
            }
            #pragma unroll
            for (int nb = 0; nb < 4; nb++) {
                int m = lane >> 3;
                int row = wn + nb * 16 + (m >> 1) * 8 + (lane & 7);
                int chunk = (kk * 2 + (m & 1)) ^ (lane & 7);
                LDSM4(bF[nb][0], bF[nb][1], bF[nb][2], bF[nb][3],
                      buf + A_STG + row * 128 + chunk * 16);
            }
            #pragma unroll
            for (int mi = 0; mi < 2; mi++)
                #pragma unroll
                for (int n8 = 0; n8 < 8; n8++)
                    mma16816(acc[mi][n8],
                             aF[mi][0], aF[mi][1], aF[mi][2], aF[mi][3],
                             bF[n8 >> 1][(n8 & 1) * 2], bF[n8 >> 1][(n8 & 1) * 2 + 1]);
        }
        __syncthreads();
        if (tid == 0 && s + NSLOT < KSTAGES) ISSUE(s + NSLOT);
    }
    #undef ISSUE

    // --- epilogue: scores -> smem (reuse pipeline region), per-query top-4
    float* sc = (float*)bufp;           // [64][SCORE_LD] = 33.3KB
    const int mrow = lane >> 2;
    const int ncol = (lane & 3) * 2;
    #pragma unroll
    for (int mi = 0; mi < 2; mi++) {
        #pragma unroll
        for (int n8 = 0; n8 < 8; n8++) {
            int m = wm + mi * 16 + mrow;
            int n = wn + n8 * 8 + ncol;
            *(float2*)&sc[m * SCORE_LD + n] = make_float2(acc[mi][n8][0], acc[mi][n8][1]);
            *(float2*)&sc[(m + 8) * SCORE_LD + n] = make_float2(acc[mi][n8][2], acc[mi][n8][3]);
        }
    }
    __syncthreads();

    // two threads per query, each scans 64 columns keeping top-4 keys
    const int q = tid >> 1;
    const int h = tid & 1;
    ull key[CPT];
    #pragma unroll
    for (int j = 0; j < CPT; j++) key[j] = 0;
    for (int c = 0; c < 64; c++) {
        int col = h * 64 + c;
        if (col >= valid) break;
        float v = sc[q * SCORE_LD + col];
        ull k = ((ull)f2sort(v) << 32) | (uint32_t)(~(uint32_t)(nBase + col));
        if (k > key[CPT - 1]) {
            bool placed = false;
            #pragma unroll
            for (int p = CPT - 1; p >= 0; p--) {
                bool upper = (p > 0) && (k > key[p - 1]);
                if (!placed) {
                    if (upper) key[p] = key[p - 1];
                    else       { key[p] = k; placed = true; }
                }
            }
        }
    }
    // partner exchange (lanes 2q, 2q+1 adjacent in same warp)
    ull pk[CPT];
    #pragma unroll
    for (int j = 0; j < CPT; j++)
        pk[j] = __shfl_down_sync(0xFFFFFFFFu, key[j], 1);
    if (h == 0) {
        ull outk[CPT];
        int ia = 0, ib = 0;
        #pragma unroll
        for (int o = 0; o < CPT; o++) {
            bool ta = (ib >= CPT) || (ia < CPT && key[ia] >= pk[ib]);
            outk[o] = ta ? key[ia++] : pk[ib++];
        }
        size_t base = ((size_t)(qBase + q) * NT + blockIdx.y) * CPT;
        #pragma unroll
        for (int j = 0; j < CPT; j++) g_ck[base + j] = outk[j];
    }
}

// ---------------------------------------------------------------------------
// Finalize (fused merge + exact rescore + gather), one block per query.
// ---------------------------------------------------------------------------
__device__ __forceinline__ void merge16(ull* dst, const ull* a, const ull* b,
                                        int la, int lb) {
    int ia = 0, ib = 0;
    #pragma unroll
    for (int o = 0; o < 16; o++) {
        bool ta = (ib >= lb) || (ia < la && a[ia] >= b[ib]);
        dst[o] = ta ? a[ia++] : b[ib++];
    }
}

__global__ __launch_bounds__(256) void finalize_kernel(
    const float* __restrict__ dk,
    const int* __restrict__ tokens,
    const int* __restrict__ mask,
    const int* __restrict__ ids,
    float* __restrict__ out
) {
    const int q = blockIdx.x;
    const int tid = threadIdx.x;
    const int wid = tid >> 5, lane = tid & 31;
    __shared__ ull bufA[2048];
    __shared__ ull bufB[2048];
    __shared__ float qrow[DIM];
    __shared__ float sval[NCAND];
    __shared__ int   sidx[NCAND];
    __shared__ float s_topv[TOPK];
    __shared__ int   s_topi[TOPK];

    // --- phase A: per-thread top-8 over candidate keys, then tree-merge
    ull loc[8];
    #pragma unroll
    for (int j = 0; j < 8; j++) loc[j] = 0;
    const ull* ck = g_ck + (size_t)q * NC;
    for (int i = tid; i < NC; i += 256) {
        ull k = ck[i];
        if (k > loc[7]) {
            bool placed = false;
            #pragma unroll
            for (int p = 7; p >= 0; p--) {
                bool upper = (p > 0) && (k > loc[p - 1]);
                if (!placed) {
                    if (upper) loc[p] = loc[p - 1];
                    else       { loc[p] = k; placed = true; }
                }
            }
        }
    }
    #pragma unroll
    for (int j = 0; j < 8; j++) bufA[tid * 8 + j] = loc[j];
    // load qrow while merge tree happens (no dependence yet)
    for (int i = tid; i < DIM; i += 256) qrow[i] = g_qn[q * DIM + i];
    __syncthreads();

    if (tid < 128) merge16(&bufB[tid * 16], &bufA[2 * tid * 8], &bufA[(2 * tid + 1) * 8], 8, 8);
    __syncthreads();
    if (tid < 64) merge16(&bufA[tid * 16], &bufB[2 * tid * 16], &bufB[(2 * tid + 1) * 16], 16, 16);
    __syncthreads();
    if (tid < 32) merge16(&bufB[tid * 16], &bufA[2 * tid * 16], &bufA[(2 * tid + 1) * 16], 16, 16);
    __syncthreads();
    if (tid < 16) merge16(&bufA[tid * 16], &bufB[2 * tid * 16], &bufB[(2 * tid + 1) * 16], 16, 16);
    __syncthreads();
    if (tid < 8)  merge16(&bufB[tid * 16], &bufA[2 * tid * 16], &bufA[(2 * tid + 1) * 16], 16, 16);
    __syncthreads();
    if (tid < 4)  merge16(&bufA[tid * 16], &bufB[2 * tid * 16], &bufB[(2 * tid + 1) * 16], 16, 16);
    __syncthreads();
    if (tid < 2)  merge16(&bufB[tid * 16], &bufA[2 * tid * 16], &bufA[(2 * tid + 1) * 16], 16, 16);
    __syncthreads();
    if (tid < 1)  merge16(&bufA[0], &bufB[0], &bufB[16], 16, 16);
    __syncthreads();

    // --- phase B: exact fp32 rescore of the 16 candidates (2 per warp)
    #pragma unroll
    for (int rep = 0; rep < 2; rep++) {
        int c = wid + rep * 8;
        int doc = (int)(~(uint32_t)(bufA[c] & 0xFFFFFFFFull));
        const float* drow = dk + (size_t)doc * DIM;
        float s = 0.f;
        #pragma unroll
        for (int e = 0; e < DIM / 32; e++)
            s = fmaf(qrow[lane + e * 32], drow[lane + e * 32], s);
        #pragma unroll
        for (int off = 16; off >= 1; off >>= 1)
            s += __shfl_xor_sync(0xFFFFFFFFu, s, off);
        if (lane == 0) { sval[c] = s * g_dinv[doc]; sidx[c] = doc; }
    }
    __syncthreads();

    // --- phase C: exact top-8 (tie -> lower index)
    if (tid == 0) {
        bool used[NCAND];
        #pragma unroll
        for (int i = 0; i < NCAND; i++) used[i] = false;
        for (int j = 0; j < TOPK; j++) {
            float bv = -FLT_MAX; int bi = 0x7FFFFFFF; int bp = -1;
            for (int i = 0; i < NCAND; i++) {
                if (used[i]) continue;
                float v = sval[i]; int ix = sidx[i];
                if (v > bv || (v == bv && ix < bi)) { bv = v; bi = ix; bp = i; }
            }
            used[bp] = true;
            s_topv[j] = bv;
            s_topi[j] = bi;
        }
    }
    __syncthreads();

    // --- phase D: gather. warp j handles output item (q, j).
    {
        const int j = wid;                 // 0..7
        const int item = q * TOPK + j;
        const int di = s_topi[j];

        #pragma unroll
        for (int r = 0; r < 4; r++) {
            int c = lane + r * 32;
            out[OFF_TOK + (size_t)item * SDOC + c] =
                (float)tokens[(size_t)di * SDOC + c];
            out[OFF_MASK + (size_t)item * SDOC + c] =
                mask[(size_t)di * SDOC + c] ? 1.0f : 0.0f;
        }
        const float* e = dk + (size_t)di * DIM;
        #pragma unroll
        for (int r = 0; r < DIM / 32; r++) {
            int c = lane + r * 32;
            out[OFF_EMB + (size_t)item * DIM + c] = e[c];
        }
        if (lane == 0) out[OFF_SCORE + item] = s_topv[j];
        if (lane == 1) out[OFF_IDS + item]   = (float)ids[di];
    }
}

// ---------------------------------------------------------------------------
extern "C" void kernel_launch(void* const* d_in, const int* in_sizes, int n_in,
                              void* d_out, int out_size) {
    const float* qe   = (const float*)d_in[0];
    const float* dk   = (const float*)d_in[1];
    const int*   tok  = (const int*)d_in[2];
    const int*   mask = (const int*)d_in[3];
    const int*   ids  = (const int*)d_in[4];
    float* out = (float*)d_out;

    // pipeline (3*24KB) also hosts the 64x130 fp32 score tile (33.3KB)
    const int dynsmem = NSLOT * STG_BYTES + 128;   // 73856 -> 3 CTAs/SM
    static int attr_done = 0;
    if (!attr_done) {
        cudaFuncSetAttribute(score_gemm_mma,
                             cudaFuncAttributeMaxDynamicSharedMemorySize, dynsmem);
        attr_done = 1;
    }

    qnorm_kernel<<<NQ, 256>>>(qe);
    docprep_kernel<<<NDPAD, 256>>>(dk);

    dim3 grid(NQT, NT);   // qtile fast-varying -> doc tile L2 reuse (8x)
    score_gemm_mma<<<grid, 128, dynsmem>>>();

    finalize_kernel<<<NQ, 256>>>(dk, tok, mask, ids, out);
}

// round 15
// speedup vs baseline: 1.8432x; 1.0196x over previous
#include <cuda_runtime.h>
#include <cuda_fp16.h>
#include <math.h>
#include <float.h>
#include <stdint.h>

// Problem constants
#define NQ 512
#define DIM 768
#define ND 100000
#define TOPK 8
#define SDOC 128

#define TILE_M 64                 // queries per CTA
#define TILE_N 128                // docs per CTA
#define NQT 8                     // 512/64 query tiles
#define NT 782                    // ceil(100000/128)
#define NDPAD (NT * 128)
#define CPT 4                     // candidates kept per (query, tile)
#define NC (NT * CPT)             // 3128 candidates per query
#define NCAND 16                  // exact-rescore set size

#define KSTAGES 12                // K=768 in 64-wide stages
#define A_STG 8192                // 64 rows x 128B
#define B_STG 16384               // 128 rows x 128B
#define STG_BYTES (A_STG + B_STG) // 24KB per stage
#define NSLOT 3

// Output layout (fp32 concat, reference return order)
#define OFF_TOK   0u
#define OFF_MASK  524288u
#define OFF_SCORE 1048576u
#define OFF_IDS   1052672u
#define OFF_EMB   1056768u

typedef unsigned long long ull;

// Scratch (device globals)
__device__ float g_qn[NQ * DIM];
__device__ __align__(128) unsigned char g_qnT[NQT * KSTAGES * A_STG];        // tiled queries (f16)
__device__ __align__(128) unsigned char g_dkT[(size_t)NT * KSTAGES * B_STG]; // 153.6MB tiled docs (f16)
__device__ float g_dinv[ND];
__device__ ull   g_ck[(size_t)NQ * NC];

// ---------------------------------------------------------------------------
// helpers
// ---------------------------------------------------------------------------
__device__ __forceinline__ uint32_t smem_u32(const void* p) {
    uint32_t a;
    asm("{ .reg .u64 t; cvta.to.shared.u64 t, %1; cvt.u32.u64 %0, t; }"
        : "=r"(a) : "l"(p));
    return a;
}
__device__ __forceinline__ uint64_t gmem_u64(const void* p) {
    uint64_t r;
    asm("cvta.to.global.u64 %0, %1;" : "=l"(r) : "l"(p));
    return r;
}
__device__ __forceinline__ uint32_t f2sort(float f) {
    uint32_t u = __float_as_uint(f);
    return (u & 0x80000000u) ? ~u : (u | 0x80000000u);
}
// tiled+swizzled byte offset of f16 element c (0..767), A tiles (64 rows)
__device__ __forceinline__ size_t tiled_off_a(int row, int c) {
    int stage = c >> 6;
    int cc = c & 63;
    int chunk = (cc >> 3) ^ (row & 7);
    return (size_t)stage * A_STG + (size_t)row * 128 + chunk * 16 + (cc & 7) * 2;
}
// B tiles (128 rows)
__device__ __forceinline__ size_t tiled_off_b(int row, int c) {
    int stage = c >> 6;
    int cc = c & 63;
    int chunk = (cc >> 3) ^ (row & 7);
    return (size_t)stage * B_STG + (size_t)row * 128 + chunk * 16 + (cc & 7) * 2;
}

#define MBAR_INIT(a, c) \
    asm volatile("mbarrier.init.shared.b64 [%0], %1;" :: "r"(a), "r"(c) : "memory")
#define MBAR_EXPECT(a, n) \
    asm volatile("mbarrier.arrive.expect_tx.shared.b64 _, [%0], %1;" :: "r"(a), "r"(n) : "memory")
__device__ __forceinline__ void mbar_wait(uint32_t mbar, uint32_t parity) {
    asm volatile(
        "{\n\t.reg .pred P1;\n\t"
        "WAIT_LOOP_%=:\n\t"
        "mbarrier.try_wait.parity.acquire.cta.shared::cta.b64 P1, [%0], %1, 0x989680;\n\t"
        "@P1 bra.uni WAIT_DONE_%=;\n\t"
        "bra.uni WAIT_LOOP_%=;\n\t"
        "WAIT_DONE_%=:\n\t}"
        :: "r"(mbar), "r"(parity) : "memory");
}
__device__ __forceinline__ void bulk_cp(uint32_t dst, uint64_t src, uint32_t bytes,
                                        uint32_t mbar) {
    asm volatile(
        "cp.async.bulk.shared::cluster.global.mbarrier::complete_tx::bytes "
        "[%0], [%1], %2, [%3];"
        :: "r"(dst), "l"(src), "r"(bytes), "r"(mbar) : "memory");
}

#define LDSM4(r0,r1,r2,r3,a) \
    asm volatile("ldmatrix.sync.aligned.m8n8.x4.shared.b16 {%0,%1,%2,%3}, [%4];" \
                 : "=r"(r0),"=r"(r1),"=r"(r2),"=r"(r3) : "r"(a))

// f16 inputs, f16 accumulators (2 c-regs of f16x2)
__device__ __forceinline__ void mma16816_f16(uint32_t* c, uint32_t a0, uint32_t a1,
                                             uint32_t a2, uint32_t a3,
                                             uint32_t b0, uint32_t b1) {
    asm volatile(
        "mma.sync.aligned.m16n8k16.row.col.f16.f16.f16.f16 "
        "{%0,%1}, {%2,%3,%4,%5}, {%6,%7}, {%0,%1};"
        : "+r"(c[0]), "+r"(c[1])
        : "r"(a0), "r"(a1), "r"(a2), "r"(a3), "r"(b0), "r"(b1));
}

// ---------------------------------------------------------------------------
// Query normalize -> fp32 (for rescore) + tiled/swizzled f16 (for GEMM)
// ---------------------------------------------------------------------------
__global__ __launch_bounds__(256) void qnorm_kernel(const float* __restrict__ q) {
    int r = blockIdx.x;
    __shared__ float red[256];
    __shared__ float s_inv;
    float v0 = q[r * DIM + threadIdx.x];
    float v1 = q[r * DIM + threadIdx.x + 256];
    float v2 = q[r * DIM + threadIdx.x + 512];
    red[threadIdx.x] = v0 * v0 + v1 * v1 + v2 * v2;
    __syncthreads();
    for (int st = 128; st >= 1; st >>= 1) {
        if (threadIdx.x < st) red[threadIdx.x] += red[threadIdx.x + st];
        __syncthreads();
    }
    if (threadIdx.x == 0) s_inv = 1.0f / fmaxf(sqrtf(red[0]), 1e-12f);
    __syncthreads();
    float inv = s_inv;
    int tile = r >> 6, row = r & 63;
    unsigned char* obase = g_qnT + (size_t)tile * KSTAGES * A_STG;
    #pragma unroll
    for (int e = 0; e < 3; e++) {
        int c = threadIdx.x + e * 256;
        float v = (e == 0 ? v0 : (e == 1 ? v1 : v2)) * inv;
        g_qn[r * DIM + c] = v;
        *(__half*)(obase + tiled_off_a(row, c)) = __float2half(v);
    }
}

// ---------------------------------------------------------------------------
// Doc prep: norm + f16 convert into tiled/swizzled layout (zero pad tail)
// ---------------------------------------------------------------------------
__global__ __launch_bounds__(256) void docprep_kernel(const float* __restrict__ dk) {
    int d = blockIdx.x;               // 0..NDPAD-1
    int tile = d >> 7, row = d & 127;
    unsigned char* obase = g_dkT + (size_t)tile * KSTAGES * B_STG;
    if (d >= ND) {
        #pragma unroll
        for (int e = 0; e < 3; e++) {
            int c = threadIdx.x + e * 256;
            *(__half*)(obase + tiled_off_b(row, c)) = __float2half(0.f);
        }
        return;
    }
    const float* srow = dk + (size_t)d * DIM;
    float v0 = srow[threadIdx.x];
    float v1 = srow[threadIdx.x + 256];
    float v2 = srow[threadIdx.x + 512];
    __shared__ float red[256];
    __shared__ float s_inv;
    red[threadIdx.x] = v0 * v0 + v1 * v1 + v2 * v2;
    __syncthreads();
    for (int st = 128; st >= 1; st >>= 1) {
        if (threadIdx.x < st) red[threadIdx.x] += red[threadIdx.x + st];
        __syncthreads();
    }
    if (threadIdx.x == 0) {
        float inv = 1.0f / fmaxf(sqrtf(red[0]), 1e-12f);
        s_inv = inv;
        g_dinv[d] = inv;
    }
    __syncthreads();
    float inv = s_inv;
    #pragma unroll
    for (int e = 0; e < 3; e++) {
        int c = threadIdx.x + e * 256;
        float v = (e == 0 ? v0 : (e == 1 ? v1 : v2)) * inv;
        *(__half*)(obase + tiled_off_b(row, c)) = __float2half(v);
    }
}

// ---------------------------------------------------------------------------
// Phase-1 GEMM: 64q x 128docs per CTA, 4 warps (warp tile 32x64),
// K=768 as 12 stages of 64, cp.async.bulk 3-slot mbarrier pipeline,
// 3 CTAs/SM. f16 inputs + f16 accumulators (testing 2x consumer-rate pipe).
// Fused per-query top-4 candidate epilogue.
// ---------------------------------------------------------------------------
#define SCORE_LD 130

__global__ __launch_bounds__(128, 3) void score_gemm_mma() {
    extern __shared__ char dynsm[];
    __shared__ __align__(8) ull s_full[NSLOT];

    const int tid  = threadIdx.x;
    const int lane = tid & 31;
    const int wid  = tid >> 5;
    const int wm   = (wid & 1) * 32;   // warp M offset (2-way)
    const int wn   = (wid >> 1) * 64;  // warp N offset (2-way)
    const int qBase = blockIdx.x * TILE_M;
    const int nBase = blockIdx.y * TILE_N;
    const int valid = min(TILE_N, ND - nBase);

    const uint32_t raw = smem_u32(dynsm);
    const uint32_t smbase = (raw + 127u) & ~127u;
    char* bufp = dynsm + (smbase - raw);

    const uint64_t srcA = gmem_u64(g_qnT) + (size_t)blockIdx.x * KSTAGES * A_STG;
    const uint64_t srcB = gmem_u64(g_dkT) + (size_t)blockIdx.y * KSTAGES * B_STG;

    if (tid == 0) {
        #pragma unroll
        for (int i = 0; i < NSLOT; i++) MBAR_INIT(smem_u32(&s_full[i]), 1);
    }
    __syncthreads();

    #define ISSUE(s) do { \
        int _slot = (s) % NSLOT; \
        uint32_t _mb = smem_u32(&s_full[_slot]); \
        uint32_t _dst = smbase + _slot * STG_BYTES; \
        MBAR_EXPECT(_mb, STG_BYTES); \
        bulk_cp(_dst, srcA + (size_t)(s) * A_STG, A_STG, _mb); \
        bulk_cp(_dst + A_STG, srcB + (size_t)(s) * B_STG, B_STG, _mb); \
    } while (0)

    if (tid == 0) { ISSUE(0); ISSUE(1); ISSUE(2); }

    uint32_t acc[2][8][2];
    #pragma unroll
    for (int mi = 0; mi < 2; mi++)
        #pragma unroll
        for (int ni = 0; ni < 8; ni++) {
            acc[mi][ni][0] = 0u;
            acc[mi][ni][1] = 0u;
        }

    for (int s = 0; s < KSTAGES; s++) {
        const int slot = s % NSLOT;
        mbar_wait(smem_u32(&s_full[slot]), (s / NSLOT) & 1);
        const uint32_t buf = smbase + slot * STG_BYTES;

        #pragma unroll
        for (int kk = 0; kk < 4; kk++) {      // four K16 blocks per 64-elem stage
            uint32_t aF[2][4], bF[4][4];
            #pragma unroll
            for (int mi = 0; mi < 2; mi++) {
                int row = wm + mi * 16 + (lane & 15);
                int chunk = (kk * 2 + (lane >> 4)) ^ (lane & 7);
                LDSM4(aF[mi][0], aF[mi][1], aF[mi][2], aF[mi][3],
                      buf + row * 128 + chunk * 16);
            }
            #pragma unroll
            for (int nb = 0; nb < 4; nb++) {
                int m = lane >> 3;
                int row = wn + nb * 16 + (m >> 1) * 8 + (lane & 7);
                int chunk = (kk * 2 + (m & 1)) ^ (lane & 7);
                LDSM4(bF[nb][0], bF[nb][1], bF[nb][2], bF[nb][3],
                      buf + A_STG + row * 128 + chunk * 16);
            }
            #pragma unroll
            for (int mi = 0; mi < 2; mi++)
                #pragma unroll
                for (int n8 = 0; n8 < 8; n8++)
                    mma16816_f16(acc[mi][n8],
                                 aF[mi][0], aF[mi][1], aF[mi][2], aF[mi][3],
                                 bF[n8 >> 1][(n8 & 1) * 2], bF[n8 >> 1][(n8 & 1) * 2 + 1]);
        }
        __syncthreads();
        if (tid == 0 && s + NSLOT < KSTAGES) ISSUE(s + NSLOT);
    }
    #undef ISSUE

    // --- epilogue: scores (f16x2 -> f32) -> smem, per-query top-4
    float* sc = (float*)bufp;           // [64][SCORE_LD] = 33.3KB
    const int mrow = lane >> 2;
    const int ncol = (lane & 3) * 2;
    #pragma unroll
    for (int mi = 0; mi < 2; mi++) {
        #pragma unroll
        for (int n8 = 0; n8 < 8; n8++) {
            int m = wm + mi * 16 + mrow;
            int n = wn + n8 * 8 + ncol;
            float2 lo = __half22float2(*(const __half2*)&acc[mi][n8][0]);
            float2 hi = __half22float2(*(const __half2*)&acc[mi][n8][1]);
            *(float2*)&sc[m * SCORE_LD + n] = lo;
            *(float2*)&sc[(m + 8) * SCORE_LD + n] = hi;
        }
    }
    __syncthreads();

    // two threads per query, each scans 64 columns keeping top-4 keys
    const int q = tid >> 1;
    const int h = tid & 1;
    ull key[CPT];
    #pragma unroll
    for (int j = 0; j < CPT; j++) key[j] = 0;
    for (int c = 0; c < 64; c++) {
        int col = h * 64 + c;
        if (col >= valid) break;
        float v = sc[q * SCORE_LD + col];
        ull k = ((ull)f2sort(v) << 32) | (uint32_t)(~(uint32_t)(nBase + col));
        if (k > key[CPT - 1]) {
            bool placed = false;
            #pragma unroll
            for (int p = CPT - 1; p >= 0; p--) {
                bool upper = (p > 0) && (k > key[p - 1]);
                if (!placed) {
                    if (upper) key[p] = key[p - 1];
                    else       { key[p] = k; placed = true; }
                }
            }
        }
    }
    // partner exchange (lanes 2q, 2q+1 adjacent in same warp)
    ull pk[CPT];
    #pragma unroll
    for (int j = 0; j < CPT; j++)
        pk[j] = __shfl_down_sync(0xFFFFFFFFu, key[j], 1);
    if (h == 0) {
        ull outk[CPT];
        int ia = 0, ib = 0;
        #pragma unroll
        for (int o = 0; o < CPT; o++) {
            bool ta = (ib >= CPT) || (ia < CPT && key[ia] >= pk[ib]);
            outk[o] = ta ? key[ia++] : pk[ib++];
        }
        size_t base = ((size_t)(qBase + q) * NT + blockIdx.y) * CPT;
        #pragma unroll
        for (int j = 0; j < CPT; j++) g_ck[base + j] = outk[j];
    }
}

// ---------------------------------------------------------------------------
// Finalize (fused merge + exact rescore + gather), one block per query.
// ---------------------------------------------------------------------------
__device__ __forceinline__ void merge16(ull* dst, const ull* a, const ull* b,
                                        int la, int lb) {
    int ia = 0, ib = 0;
    #pragma unroll
    for (int o = 0; o < 16; o++) {
        bool ta = (ib >= lb) || (ia < la && a[ia] >= b[ib]);
        dst[o] = ta ? a[ia++] : b[ib++];
    }
}

__global__ __launch_bounds__(256) void finalize_kernel(
    const float* __restrict__ dk,
    const int* __restrict__ tokens,
    const int* __restrict__ mask,
    const int* __restrict__ ids,
    float* __restrict__ out
) {
    const int q = blockIdx.x;
    const int tid = threadIdx.x;
    const int wid = tid >> 5, lane = tid & 31;
    __shared__ ull bufA[2048];
    __shared__ ull bufB[2048];
    __shared__ float qrow[DIM];
    __shared__ float sval[NCAND];
    __shared__ int   sidx[NCAND];
    __shared__ float s_topv[TOPK];
    __shared__ int   s_topi[TOPK];

    // --- phase A: per-thread top-8 over candidate keys, then tree-merge
    ull loc[8];
    #pragma unroll
    for (int j = 0; j < 8; j++) loc[j] = 0;
    const ull* ck = g_ck + (size_t)q * NC;
    for (int i = tid; i < NC; i += 256) {
        ull k = ck[i];
        if (k > loc[7]) {
            bool placed = false;
            #pragma unroll
            for (int p = 7; p >= 0; p--) {
                bool upper = (p > 0) && (k > loc[p - 1]);
                if (!placed) {
                    if (upper) loc[p] = loc[p - 1];
                    else       { loc[p] = k; placed = true; }
                }
            }
        }
    }
    #pragma unroll
    for (int j = 0; j < 8; j++) bufA[tid * 8 + j] = loc[j];
    // load qrow while merge tree happens (no dependence yet)
    for (int i = tid; i < DIM; i += 256) qrow[i] = g_qn[q * DIM + i];
    __syncthreads();

    if (tid < 128) merge16(&bufB[tid * 16], &bufA[2 * tid * 8], &bufA[(2 * tid + 1) * 8], 8, 8);
    __syncthreads();
    if (tid < 64) merge16(&bufA[tid * 16], &bufB[2 * tid * 16], &bufB[(2 * tid + 1) * 16], 16, 16);
    __syncthreads();
    if (tid < 32) merge16(&bufB[tid * 16], &bufA[2 * tid * 16], &bufA[(2 * tid + 1) * 16], 16, 16);
    __syncthreads();
    if (tid < 16) merge16(&bufA[tid * 16], &bufB[2 * tid * 16], &bufB[(2 * tid + 1) * 16], 16, 16);
    __syncthreads();
    if (tid < 8)  merge16(&bufB[tid * 16], &bufA[2 * tid * 16], &bufA[(2 * tid + 1) * 16], 16, 16);
    __syncthreads();
    if (tid < 4)  merge16(&bufA[tid * 16], &bufB[2 * tid * 16], &bufB[(2 * tid + 1) * 16], 16, 16);
    __syncthreads();
    if (tid < 2)  merge16(&bufB[tid * 16], &bufA[2 * tid * 16], &bufA[(2 * tid + 1) * 16], 16, 16);
    __syncthreads();
    if (tid < 1)  merge16(&bufA[0], &bufB[0], &bufB[16], 16, 16);
    __syncthreads();

    // --- phase B: exact fp32 rescore of the 16 candidates (2 per warp)
    #pragma unroll
    for (int rep = 0; rep < 2; rep++) {
        int c = wid + rep * 8;
        int doc = (int)(~(uint32_t)(bufA[c] & 0xFFFFFFFFull));
        const float* drow = dk + (size_t)doc * DIM;
        float s = 0.f;
        #pragma unroll
        for (int e = 0; e < DIM / 32; e++)
            s = fmaf(qrow[lane + e * 32], drow[lane + e * 32], s);
        #pragma unroll
        for (int off = 16; off >= 1; off >>= 1)
            s += __shfl_xor_sync(0xFFFFFFFFu, s, off);
        if (lane == 0) { sval[c] = s * g_dinv[doc]; sidx[c] = doc; }
    }
    __syncthreads();

    // --- phase C: exact top-8 (tie -> lower index)
    if (tid == 0) {
        bool used[NCAND];
        #pragma unroll
        for (int i = 0; i < NCAND; i++) used[i] = false;
        for (int j = 0; j < TOPK; j++) {
            float bv = -FLT_MAX; int bi = 0x7FFFFFFF; int bp = -1;
            for (int i = 0; i < NCAND; i++) {
                if (used[i]) continue;
                float v = sval[i]; int ix = sidx[i];
                if (v > bv || (v == bv && ix < bi)) { bv = v; bi = ix; bp = i; }
            }
            used[bp] = true;
            s_topv[j] = bv;
            s_topi[j] = bi;
        }
    }
    __syncthreads();

    // --- phase D: gather. warp j handles output item (q, j).
    {
        const int j = wid;                 // 0..7
        const int item = q * TOPK + j;
        const int di = s_topi[j];

        #pragma unroll
        for (int r = 0; r < 4; r++) {
            int c = lane + r * 32;
            out[OFF_TOK + (size_t)item * SDOC + c] =
                (float)tokens[(size_t)di * SDOC + c];
            out[OFF_MASK + (size_t)item * SDOC + c] =
                mask[(size_t)di * SDOC + c] ? 1.0f : 0.0f;
        }
        const float* e = dk + (size_t)di * DIM;
        #pragma unroll
        for (int r = 0; r < DIM / 32; r++) {
            int c = lane + r * 32;
            out[OFF_EMB + (size_t)item * DIM + c] = e[c];
        }
        if (lane == 0) out[OFF_SCORE + item] = s_topv[j];
        if (lane == 1) out[OFF_IDS + item]   = (float)ids[di];
    }
}

// ---------------------------------------------------------------------------
extern "C" void kernel_launch(void* const* d_in, const int* in_sizes, int n_in,
                              void* d_out, int out_size) {
    const float* qe   = (const float*)d_in[0];
    const float* dk   = (const float*)d_in[1];
    const int*   tok  = (const int*)d_in[2];
    const int*   mask = (const int*)d_in[3];
    const int*   ids  = (const int*)d_in[4];
    float* out = (float*)d_out;

    // pipeline (3*24KB) also hosts the 64x130 fp32 score tile (33.3KB)
    const int dynsmem = NSLOT * STG_BYTES + 128;   // 73856 -> 3 CTAs/SM
    static int attr_done = 0;
    if (!attr_done) {
        cudaFuncSetAttribute(score_gemm_mma,
                             cudaFuncAttributeMaxDynamicSharedMemorySize, dynsmem);
        attr_done = 1;
    }

    qnorm_kernel<<<NQ, 256>>>(qe);
    docprep_kernel<<<NDPAD, 256>>>(dk);

    dim3 grid(NQT, NT);   // qtile fast-varying -> doc tile L2 reuse (8x)
    score_gemm_mma<<<grid, 128, dynsmem>>>();

    finalize_kernel<<<NQ, 256>>>(dk, tok, mask, ids, out);
}